// round 6
// baseline (speedup 1.0000x reference)
#include <cuda_runtime.h>
#include <math.h>

#define BV 4
#define NV 4096
#define NNV (BV*NV)

// ---------------- scratch (device globals; no allocation allowed) ----------
__device__ float g_h18[(size_t)BV*18*NV];
__device__ float g_x1 [(size_t)BV*64*NV];
__device__ float g_x2 [(size_t)BV*128*NV];
__device__ float g_h3 [(size_t)BV*256*NV];
__device__ float g_Q  [(size_t)BV*128*NV];
__device__ float g_Kt [(size_t)BV*128*NV];
__device__ float g_V  [(size_t)BV*128*NV];
__device__ float g_O  [(size_t)BV*128*NV];
__device__ float g_S  [(size_t)BV*NV*NV];      // 268 MB attention matrix
__device__ float g_P8 [(size_t)BV*8*128*NV];   // 64 MB k-split partials for O
__device__ float g_h4 [(size_t)BV*256*NV];
__device__ float g_a  [(size_t)BV*64*NV];
__device__ float g_sc [(size_t)BV*NV];
__device__ float g_mean[256];
__device__ float g_rstd[256];
__device__ float g_pooled[BV*256];

// ---------------- KNN + local diffs ----------------------------------------
__global__ void knn_kernel(const float* __restrict__ x)
{
    __shared__ float sx[NV], sy[NV], sz[NV];
    int b = blockIdx.y;
    const float* xb = x + (size_t)b * NV * 9;
    for (int m = threadIdx.x; m < NV; m += blockDim.x) {
        sx[m] = xb[(size_t)m*9 + 0];
        sy[m] = xb[(size_t)m*9 + 1];
        sz[m] = xb[(size_t)m*9 + 2];
    }
    __syncthreads();

    int n = blockIdx.x * blockDim.x + threadIdx.x;
    float qx = sx[n], qy = sy[n], qz = sz[n];
    float qs = fmaf(qz, qz, fmaf(qy, qy, qx*qx));

    float bd[9]; int bi[9];
#pragma unroll
    for (int j = 0; j < 9; j++) { bd[j] = 3.4e38f; bi[j] = 0; }

#pragma unroll 4
    for (int m = 0; m < NV; m++) {
        float mx = sx[m], my = sy[m], mz = sz[m];
        float ms  = fmaf(mz, mz, fmaf(my, my, mx*mx));
        float dot = fmaf(mz, qz, fmaf(my, qy, mx*qx));
        float d2  = fmaf(-2.f, dot, qs + ms);
        d2 = fmaxf(d2, 0.f);
        if (d2 < bd[8]) {
            bool pl = false;
#pragma unroll
            for (int j = 8; j >= 1; j--) {
                if (!pl) {
                    if (d2 < bd[j-1]) { bd[j] = bd[j-1]; bi[j] = bi[j-1]; }
                    else              { bd[j] = d2;      bi[j] = m; pl = true; }
                }
            }
            if (!pl) { bd[0] = d2; bi[0] = m; }
        }
    }

    float acc[9];
#pragma unroll
    for (int c = 0; c < 9; c++) acc[c] = 0.f;
#pragma unroll
    for (int j = 1; j < 9; j++) {
        const float* xr = xb + (size_t)bi[j] * 9;
#pragma unroll
        for (int c = 0; c < 9; c++) acc[c] += xr[c];
    }
    const float* xn = xb + (size_t)n * 9;
#pragma unroll
    for (int c = 0; c < 9; c++) {
        float xc = xn[c];
        g_h18[((size_t)b*18 + c    )*NV + n] = acc[c]*0.125f - xc;
        g_h18[((size_t)b*18 + 9 + c)*NV + n] = xc;
    }
}

// ---------------- generic tiled GEMM (64x64, used for small/odd shapes) -----
template<bool AKI, bool BKI, int ACT>
__global__ void __launch_bounds__(256)
gemm_k(const float* __restrict__ A, const float* __restrict__ B,
       const float* __restrict__ bias, const float* __restrict__ res,
       float* __restrict__ C,
       int M, int K,
       long long sAi, long long sAk, long long sBk, long long sBj,
       long long ldC, long long bA, long long bB, long long bC)
{
    __shared__ __align__(16) float As[16*66];
    __shared__ __align__(16) float Bs[16*66];
    int b  = blockIdx.z;
    const float* Ab = A + (long long)b * bA;
    const float* Bb = B + (long long)b * bB;
    float* Cb = C + (long long)b * bC;
    int i0 = blockIdx.y * 64, j0 = blockIdx.x * 64;
    int tid = threadIdx.x;
    int tx = tid & 15, ty = tid >> 4;

    float acc[4][4];
#pragma unroll
    for (int r = 0; r < 4; r++)
#pragma unroll
        for (int c = 0; c < 4; c++) acc[r][c] = 0.f;

    for (int k0 = 0; k0 < K; k0 += 16) {
#pragma unroll
        for (int l = 0; l < 4; l++) {
            int t = tid + l*256;
            int kc, ii;
            if (AKI) { ii = t >> 4; kc = t & 15; } else { kc = t >> 6; ii = t & 63; }
            float av = 0.f;
            if (k0 + kc < K) av = Ab[(long long)(i0+ii)*sAi + (long long)(k0+kc)*sAk];
            As[kc*66 + ii] = av;
            int jj;
            if (BKI) { jj = t >> 4; kc = t & 15; } else { kc = t >> 6; jj = t & 63; }
            float bv = 0.f;
            if (k0 + kc < K) bv = Bb[(long long)(k0+kc)*sBk + (long long)(j0+jj)*sBj];
            Bs[kc*66 + jj] = bv;
        }
        __syncthreads();
#pragma unroll
        for (int kc = 0; kc < 16; kc++) {
            float2 a0 = *(const float2*)&As[kc*66 + ty*4];
            float2 a1 = *(const float2*)&As[kc*66 + ty*4 + 2];
            float2 b0 = *(const float2*)&Bs[kc*66 + tx*4];
            float2 b1 = *(const float2*)&Bs[kc*66 + tx*4 + 2];
            float ar[4] = {a0.x, a0.y, a1.x, a1.y};
            float br[4] = {b0.x, b0.y, b1.x, b1.y};
#pragma unroll
            for (int r = 0; r < 4; r++)
#pragma unroll
                for (int c = 0; c < 4; c++)
                    acc[r][c] = fmaf(ar[r], br[c], acc[r][c]);
        }
        __syncthreads();
    }

#pragma unroll
    for (int r = 0; r < 4; r++) {
        int i = i0 + ty*4 + r;
        float bv = bias ? bias[i] : 0.f;
#pragma unroll
        for (int c = 0; c < 4; c++) {
            int j = j0 + tx*4 + c;
            float v = acc[r][c] + bv;
            if (res) v += res[(long long)b*bC + (long long)i*ldC + j];
            if (ACT == 1) v = fmaxf(v, 0.f);
            Cb[(long long)i*ldC + j] = v;
        }
    }
}

// ---------------- big tiled GEMM: 128x128 tile, 8x8/thread, k-chunk 8 -------
// Double-buffered smem pipeline: prefetch chunk k+1 into registers during
// compute of chunk k; one __syncthreads per iteration. FMA order identical
// to the unpipelined version.
// C[z][i][j] = sum_{k in [s*KS,(s+1)*KS)} A[b][i,k]*B[b][k,j]  (+bias/res/act)
// z = b*NS + s. Requires: j-dim % 128 == 0, KS % 8 == 0. No bounds checks.
template<bool AKI, bool BKI, int ACT>
__global__ void __launch_bounds__(256, 2)
gemm128(const float* __restrict__ A, const float* __restrict__ B,
        const float* __restrict__ bias, const float* __restrict__ res,
        float* __restrict__ C,
        int KS, int NS,
        long long sAi, long long sAk, long long sBk, long long sBj,
        long long ldC, long long bA, long long bB, long long bCz)
{
    __shared__ __align__(16) float As[2][8][132];
    __shared__ __align__(16) float Bs[2][8][132];
    int bz = blockIdx.z;
    int b  = bz / NS;
    int s  = bz - b * NS;
    const float* Ab = A + (long long)b * bA;
    const float* Bb = B + (long long)b * bB;
    float* Cb = C + (long long)bz * bCz;
    int i0 = blockIdx.y * 128, j0 = blockIdx.x * 128;
    int kstart = s * KS;
    int tid = threadIdx.x;
    int tx = tid & 15, ty = tid >> 4;

    // per-thread load coordinates for the 4 load slots (compile-time pattern)
    int akc[4], aii[4], bkc[4], bjj[4];
#pragma unroll
    for (int l = 0; l < 4; l++) {
        int t = tid + l*256;
        if (AKI) { akc[l] = t & 7; aii[l] = t >> 3; } else { aii[l] = t & 127; akc[l] = t >> 7; }
        if (BKI) { bkc[l] = t & 7; bjj[l] = t >> 3; } else { bjj[l] = t & 127; bkc[l] = t >> 7; }
    }

    float acc[8][8];
#pragma unroll
    for (int r = 0; r < 8; r++)
#pragma unroll
        for (int c = 0; c < 8; c++) acc[r][c] = 0.f;

    // prologue: load chunk 0 into buffer 0
#pragma unroll
    for (int l = 0; l < 4; l++) {
        As[0][akc[l]][aii[l]] = Ab[(long long)(i0+aii[l])*sAi + (long long)(kstart+akc[l])*sAk];
        Bs[0][bkc[l]][bjj[l]] = Bb[(long long)(kstart+bkc[l])*sBk + (long long)(j0+bjj[l])*sBj];
    }
    __syncthreads();

    int buf = 0;
    for (int k0 = 0; k0 < KS; k0 += 8) {
        bool has_next = (k0 + 8 < KS);
        float pa[4], pb[4];
        if (has_next) {
            int kb = kstart + k0 + 8;
#pragma unroll
            for (int l = 0; l < 4; l++) {
                pa[l] = Ab[(long long)(i0+aii[l])*sAi + (long long)(kb+akc[l])*sAk];
                pb[l] = Bb[(long long)(kb+bkc[l])*sBk + (long long)(j0+bjj[l])*sBj];
            }
        }
#pragma unroll
        for (int kc = 0; kc < 8; kc++) {
            float4 a0 = *(const float4*)&As[buf][kc][ty*4];
            float4 a1 = *(const float4*)&As[buf][kc][64 + ty*4];
            float4 b0 = *(const float4*)&Bs[buf][kc][tx*4];
            float4 b1 = *(const float4*)&Bs[buf][kc][64 + tx*4];
            float ar[8] = {a0.x,a0.y,a0.z,a0.w, a1.x,a1.y,a1.z,a1.w};
            float br[8] = {b0.x,b0.y,b0.z,b0.w, b1.x,b1.y,b1.z,b1.w};
#pragma unroll
            for (int r = 0; r < 8; r++)
#pragma unroll
                for (int c = 0; c < 8; c++)
                    acc[r][c] = fmaf(ar[r], br[c], acc[r][c]);
        }
        if (has_next) {
            int nb = buf ^ 1;
#pragma unroll
            for (int l = 0; l < 4; l++) {
                As[nb][akc[l]][aii[l]] = pa[l];
                Bs[nb][bkc[l]][bjj[l]] = pb[l];
            }
            __syncthreads();
            buf = nb;
        }
    }

#pragma unroll
    for (int r = 0; r < 8; r++) {
        int i = i0 + (r < 4 ? ty*4 + r : 64 + ty*4 + (r-4));
        float bv = bias ? bias[i] : 0.f;
#pragma unroll
        for (int c = 0; c < 8; c++) {
            int j = j0 + (c < 4 ? tx*4 + c : 64 + tx*4 + (c-4));
            float v = acc[r][c] + bv;
            if (res) v += res[(long long)bz*bCz + (long long)i*ldC + j];
            if (ACT == 1) v = fmaxf(v, 0.f);
            Cb[(long long)i*ldC + j] = v;
        }
    }
}

// ---------------- deterministic k-split reduction for O ----------------------
// O[b][h][n] = sum_{s=0..7} part[b*8+s][h][n]; per-b inner size = 128*4096 = 2^19
__global__ void reduce8(const float* __restrict__ part, float* __restrict__ O)
{
    int idx = blockIdx.x * 256 + threadIdx.x;          // 4*2^19 total
    int b   = idx >> 19;
    int off = idx & ((1 << 19) - 1);
    const float* p = part + ((long long)b * 8) * (128LL * NV) + off;
    float acc = 0.f;
#pragma unroll
    for (int s = 0; s < 8; s++) acc += p[(long long)s * 128 * NV];
    O[idx] = acc;
}

// ---------------- BN statistics (fp64, deterministic) -----------------------
__global__ void bn_stats(const float* __restrict__ y, int Co)
{
    int ch = blockIdx.x, tid = threadIdx.x;
    double s = 0.0, s2 = 0.0;
    for (int t = tid; t < NNV; t += 256) {
        int b = t >> 12, n = t & 4095;
        float v = y[((size_t)b*Co + ch)*NV + n];
        s += v; s2 += (double)v * (double)v;
    }
    __shared__ double rs[256], rq[256];
    rs[tid] = s; rq[tid] = s2; __syncthreads();
    for (int st = 128; st > 0; st >>= 1) {
        if (tid < st) { rs[tid] += rs[tid+st]; rq[tid] += rq[tid+st]; }
        __syncthreads();
    }
    if (tid == 0) {
        double m = rs[0] / (double)NNV;
        double var = rq[0] / (double)NNV - m*m;
        g_mean[ch] = (float)m;
        g_rstd[ch] = (float)(1.0 / sqrt(var + 1e-5));
    }
}

__global__ void bn_apply(float* __restrict__ y, const float* __restrict__ gm,
                         const float* __restrict__ bt, int Co)
{
    int idx = blockIdx.x * 256 + threadIdx.x;
    if (idx >= Co * NNV) return;
    int ch = (idx >> 12) % Co;      // layout (b, Co, n)
    float v = y[idx];
    v = gm[ch] * (v - g_mean[ch]) * g_rstd[ch] + bt[ch];
    y[idx] = fmaxf(v, 0.f);
}

// ---------------- row softmax over 4096 (in place) ---------------------------
__global__ void softmax_row(float* __restrict__ S)
{
    float* p = S + (size_t)blockIdx.x * 4096;
    int tid = threadIdx.x;
    float v[16];
    float mx = -3.4e38f;
#pragma unroll
    for (int l = 0; l < 16; l++) { v[l] = p[tid + l*256]; mx = fmaxf(mx, v[l]); }
    __shared__ float red[256];
    red[tid] = mx; __syncthreads();
    for (int s = 128; s > 0; s >>= 1) {
        if (tid < s) red[tid] = fmaxf(red[tid], red[tid+s]);
        __syncthreads();
    }
    mx = red[0]; __syncthreads();
    float sum = 0.f;
#pragma unroll
    for (int l = 0; l < 16; l++) { v[l] = expf(v[l] - mx); sum += v[l]; }
    red[tid] = sum; __syncthreads();
    for (int s = 128; s > 0; s >>= 1) {
        if (tid < s) red[tid] += red[tid+s];
        __syncthreads();
    }
    float inv = 1.0f / red[0];
#pragma unroll
    for (int l = 0; l < 16; l++) p[tid + l*256] = v[l] * inv;
}

// ---------------- attention-pool tail ----------------------------------------
__global__ void score_kernel(const float* __restrict__ a, const float* __restrict__ aw2,
                             const float* __restrict__ ab2, float* __restrict__ s)
{
    int t = blockIdx.x * 256 + threadIdx.x;       // 16384
    int b = t >> 12, n = t & 4095;
    float acc = ab2[0];
#pragma unroll 8
    for (int c = 0; c < 64; c++) acc += aw2[c] * a[((size_t)b*64 + c)*NV + n];
    s[t] = acc;
}

__global__ void pool_kernel(const float* __restrict__ h, const float* __restrict__ w,
                            float* __restrict__ pooled)
{
    int c = blockIdx.x, b = blockIdx.y, tid = threadIdx.x;
    const float* hp = h + ((size_t)b*256 + c)*NV;
    const float* wp = w + (size_t)b*NV;
    float acc = 0.f;
    for (int n = tid; n < NV; n += 256) acc = fmaf(hp[n], wp[n], acc);
    __shared__ float red[256];
    red[tid] = acc; __syncthreads();
    for (int s = 128; s > 0; s >>= 1) {
        if (tid < s) red[tid] += red[tid+s];
        __syncthreads();
    }
    if (tid == 0) pooled[b*256 + c] = red[0];
}

__global__ void fc_kernel(const float* __restrict__ pooled, const float* __restrict__ fcw,
                          const float* __restrict__ fcb, float* __restrict__ out)
{
    int b = blockIdx.x, j = threadIdx.x;          // 256 per block
    __shared__ float sp[256];
    sp[j] = pooled[b*256 + j]; __syncthreads();
    float acc = fcb[j];
#pragma unroll 8
    for (int c = 0; c < 256; c++) acc = fmaf(sp[c], fcw[j*256 + c], acc);
    out[b*256 + j] = fmaxf(acc, 0.f);
}

// ---------------- host launch ------------------------------------------------
static float* sym_addr(const void* s)
{
    void* p = nullptr;
    cudaGetSymbolAddress(&p, s);
    return (float*)p;
}

extern "C" void kernel_launch(void* const* d_in, const int* in_sizes, int n_in,
                              void* d_out, int out_size)
{
    const float* x   = (const float*)d_in[0];
    const float* w1  = (const float*)d_in[1];
    const float* b1  = (const float*)d_in[2];
    const float* g1  = (const float*)d_in[3];
    const float* be1 = (const float*)d_in[4];
    const float* w2  = (const float*)d_in[5];
    const float* b2  = (const float*)d_in[6];
    const float* g2  = (const float*)d_in[7];
    const float* be2 = (const float*)d_in[8];
    const float* w3  = (const float*)d_in[9];
    const float* b3  = (const float*)d_in[10];
    const float* g3  = (const float*)d_in[11];
    const float* be3 = (const float*)d_in[12];
    const float* qw  = (const float*)d_in[13];
    const float* qb  = (const float*)d_in[14];
    const float* kw  = (const float*)d_in[15];
    const float* kb  = (const float*)d_in[16];
    const float* vw  = (const float*)d_in[17];
    const float* vb  = (const float*)d_in[18];
    const float* fw  = (const float*)d_in[19];
    const float* fb  = (const float*)d_in[20];
    const float* aw1 = (const float*)d_in[21];
    const float* ab1 = (const float*)d_in[22];
    const float* aw2 = (const float*)d_in[23];
    const float* ab2 = (const float*)d_in[24];
    const float* fcw = (const float*)d_in[25];
    const float* fcb = (const float*)d_in[26];
    float* out = (float*)d_out;

    float* h18 = sym_addr(g_h18);
    float* x1  = sym_addr(g_x1);
    float* x2  = sym_addr(g_x2);
    float* h3  = sym_addr(g_h3);
    float* Qp  = sym_addr(g_Q);
    float* Kp  = sym_addr(g_Kt);
    float* Vp  = sym_addr(g_V);
    float* Op  = sym_addr(g_O);
    float* Sp  = sym_addr(g_S);
    float* P8  = sym_addr(g_P8);
    float* h4  = sym_addr(g_h4);
    float* ap  = sym_addr(g_a);
    float* sp  = sym_addr(g_sc);
    float* pp  = sym_addr(g_pooled);

    const long long N = NV;

    // 1) KNN + local diff features -> (4,18,4096)
    knn_kernel<<<dim3(16, 4), 256>>>(x);

    // 2) conv1 (18->64) + BN + ReLU (K=18: keep 64x64 kernel w/ bounds checks)
    gemm_k<false,false,0><<<dim3(64,1,4),256>>>(w1, h18, b1, nullptr, x1,
        64, 18, 18,1, N,1, N, 0, 18*N, 64*N);
    bn_stats<<<64,256>>>(x1, 64);
    bn_apply<<<(64*NNV+255)/256,256>>>(x1, g1, be1, 64);

    // 3) conv2 (64->128): A=w2 (k-contig), B=x1 (j-contig)
    gemm128<true,false,0><<<dim3(32,1,4),256>>>(w2, x1, b2, nullptr, x2,
        64, 1, 64,1, N,1, N, 0, 64*N, 128*N);
    bn_stats<<<128,256>>>(x2, 128);
    bn_apply<<<(128*NNV+255)/256,256>>>(x2, g2, be2, 128);

    // 4) conv3 (128->256)
    gemm128<true,false,0><<<dim3(32,2,4),256>>>(w3, x2, b3, nullptr, h3,
        128, 1, 128,1, N,1, N, 0, 128*N, 256*N);
    bn_stats<<<256,256>>>(h3, 256);
    bn_apply<<<(256*NNV+255)/256,256>>>(h3, g3, be3, 256);

    // 5) Q, K, V projections (256->128)
    gemm128<true,false,0><<<dim3(32,1,4),256>>>(qw, h3, qb, nullptr, Qp,
        256, 1, 256,1, N,1, N, 0, 256*N, 128*N);
    gemm128<true,false,0><<<dim3(32,1,4),256>>>(kw, h3, kb, nullptr, Kp,
        256, 1, 256,1, N,1, N, 0, 256*N, 128*N);
    gemm128<true,false,0><<<dim3(32,1,4),256>>>(vw, h3, vb, nullptr, Vp,
        256, 1, 256,1, N,1, N, 0, 256*N, 128*N);

    // 6) S = Q^T K  (b, n, m): A=Q (i=n contig), B=K (j=m contig), K=128
    gemm128<false,false,0><<<dim3(32,32,4),256>>>(Qp, Kp, nullptr, nullptr, Sp,
        128, 1, 1,N, N,1, N, 128*N, 128*N, (long long)N*N);

    // 7) softmax over m
    softmax_row<<<16384,256>>>(Sp);

    // 8) O[h,n] = sum_m V[h,m] P[n,m] — k-split x8 into partials, then reduce.
    //    A=V (sAi=N, k contig), B=P (sBk=1, sBj=N, k contig). z = b*8+s.
    gemm128<true,true,0><<<dim3(32,1,32),256>>>(Vp, Sp, nullptr, nullptr, P8,
        512, 8, N,1, 1,N, N, 128*N, (long long)N*N, 128*N);
    reduce8<<<(BV*128*NV)/256, 256>>>(P8, Op);

    // 9) h4 = conv(O, fw) + fb + h3 (residual)
    gemm128<true,false,0><<<dim3(32,2,4),256>>>(fw, Op, fb, h3, h4,
        128, 1, 128,1, N,1, N, 0, 128*N, 256*N);

    // 10) a = relu(conv(h4, aw1))  (M=64: keep 64x64 kernel)
    gemm_k<false,false,1><<<dim3(64,1,4),256>>>(aw1, h4, ab1, nullptr, ap,
        64, 256, 256,1, N,1, N, 0, 256*N, 64*N);

    // 11) scores, softmax over n, weighted pool, final FC
    score_kernel<<<64,256>>>(ap, aw2, ab2, sp);
    softmax_row<<<4,256>>>(sp);
    pool_kernel<<<dim3(256,4),256>>>(h4, sp, pp);
    fc_kernel<<<4,256>>>(pp, fcw, fcb, out);
}

// round 9
// speedup vs baseline: 1.3417x; 1.3417x over previous
#include <cuda_runtime.h>
#include <cuda_bf16.h>
#include <math.h>

#define BV 4
#define NV 4096
#define NNV (BV*NV)

// ---------------- scratch (device globals; no allocation allowed) ----------
__device__ float g_h18[(size_t)BV*18*NV];
__device__ float g_x1 [(size_t)BV*64*NV];
__device__ float g_x2 [(size_t)BV*128*NV];
__device__ float g_h3 [(size_t)BV*256*NV];
__device__ float g_Q  [(size_t)BV*128*NV];
__device__ float g_Kt [(size_t)BV*128*NV];
__device__ float g_V  [(size_t)BV*128*NV];
__device__ float g_O  [(size_t)BV*128*NV];
__device__ float g_S  [(size_t)BV*NV*NV];      // 268 MB attention matrix
__device__ float g_P8 [(size_t)BV*8*128*NV];   // 64 MB k-split partials for O
__device__ float g_h4 [(size_t)BV*256*NV];
__device__ float g_a  [(size_t)BV*64*NV];
__device__ float g_sc [(size_t)BV*NV];
__device__ float g_mean[256];
__device__ float g_rstd[256];
__device__ float g_pooled[BV*256];

// ---------------- KNN + local diffs ----------------------------------------
__global__ void knn_kernel(const float* __restrict__ x)
{
    __shared__ float sx[NV], sy[NV], sz[NV];
    int b = blockIdx.y;
    const float* xb = x + (size_t)b * NV * 9;
    for (int m = threadIdx.x; m < NV; m += blockDim.x) {
        sx[m] = xb[(size_t)m*9 + 0];
        sy[m] = xb[(size_t)m*9 + 1];
        sz[m] = xb[(size_t)m*9 + 2];
    }
    __syncthreads();

    int n = blockIdx.x * blockDim.x + threadIdx.x;
    float qx = sx[n], qy = sy[n], qz = sz[n];
    float qs = fmaf(qz, qz, fmaf(qy, qy, qx*qx));

    float bd[9]; int bi[9];
#pragma unroll
    for (int j = 0; j < 9; j++) { bd[j] = 3.4e38f; bi[j] = 0; }

#pragma unroll 4
    for (int m = 0; m < NV; m++) {
        float mx = sx[m], my = sy[m], mz = sz[m];
        float ms  = fmaf(mz, mz, fmaf(my, my, mx*mx));
        float dot = fmaf(mz, qz, fmaf(my, qy, mx*qx));
        float d2  = fmaf(-2.f, dot, qs + ms);
        d2 = fmaxf(d2, 0.f);
        if (d2 < bd[8]) {
            bool pl = false;
#pragma unroll
            for (int j = 8; j >= 1; j--) {
                if (!pl) {
                    if (d2 < bd[j-1]) { bd[j] = bd[j-1]; bi[j] = bi[j-1]; }
                    else              { bd[j] = d2;      bi[j] = m; pl = true; }
                }
            }
            if (!pl) { bd[0] = d2; bi[0] = m; }
        }
    }

    float acc[9];
#pragma unroll
    for (int c = 0; c < 9; c++) acc[c] = 0.f;
#pragma unroll
    for (int j = 1; j < 9; j++) {
        const float* xr = xb + (size_t)bi[j] * 9;
#pragma unroll
        for (int c = 0; c < 9; c++) acc[c] += xr[c];
    }
    const float* xn = xb + (size_t)n * 9;
#pragma unroll
    for (int c = 0; c < 9; c++) {
        float xc = xn[c];
        g_h18[((size_t)b*18 + c    )*NV + n] = acc[c]*0.125f - xc;
        g_h18[((size_t)b*18 + 9 + c)*NV + n] = xc;
    }
}

// ---------------- generic tiled GEMM (64x64, small/odd shapes) --------------
template<bool AKI, bool BKI, int ACT>
__global__ void __launch_bounds__(256)
gemm_k(const float* __restrict__ A, const float* __restrict__ B,
       const float* __restrict__ bias, const float* __restrict__ res,
       float* __restrict__ C,
       int M, int K,
       long long sAi, long long sAk, long long sBk, long long sBj,
       long long ldC, long long bA, long long bB, long long bC)
{
    __shared__ __align__(16) float As[16*66];
    __shared__ __align__(16) float Bs[16*66];
    int b  = blockIdx.z;
    const float* Ab = A + (long long)b * bA;
    const float* Bb = B + (long long)b * bB;
    float* Cb = C + (long long)b * bC;
    int i0 = blockIdx.y * 64, j0 = blockIdx.x * 64;
    int tid = threadIdx.x;
    int tx = tid & 15, ty = tid >> 4;

    float acc[4][4];
#pragma unroll
    for (int r = 0; r < 4; r++)
#pragma unroll
        for (int c = 0; c < 4; c++) acc[r][c] = 0.f;

    for (int k0 = 0; k0 < K; k0 += 16) {
#pragma unroll
        for (int l = 0; l < 4; l++) {
            int t = tid + l*256;
            int kc, ii;
            if (AKI) { ii = t >> 4; kc = t & 15; } else { kc = t >> 6; ii = t & 63; }
            float av = 0.f;
            if (k0 + kc < K) av = Ab[(long long)(i0+ii)*sAi + (long long)(k0+kc)*sAk];
            As[kc*66 + ii] = av;
            int jj;
            if (BKI) { jj = t >> 4; kc = t & 15; } else { kc = t >> 6; jj = t & 63; }
            float bv = 0.f;
            if (k0 + kc < K) bv = Bb[(long long)(k0+kc)*sBk + (long long)(j0+jj)*sBj];
            Bs[kc*66 + jj] = bv;
        }
        __syncthreads();
#pragma unroll
        for (int kc = 0; kc < 16; kc++) {
            float2 a0 = *(const float2*)&As[kc*66 + ty*4];
            float2 a1 = *(const float2*)&As[kc*66 + ty*4 + 2];
            float2 b0 = *(const float2*)&Bs[kc*66 + tx*4];
            float2 b1 = *(const float2*)&Bs[kc*66 + tx*4 + 2];
            float ar[4] = {a0.x, a0.y, a1.x, a1.y};
            float br[4] = {b0.x, b0.y, b1.x, b1.y};
#pragma unroll
            for (int r = 0; r < 4; r++)
#pragma unroll
                for (int c = 0; c < 4; c++)
                    acc[r][c] = fmaf(ar[r], br[c], acc[r][c]);
        }
        __syncthreads();
    }

#pragma unroll
    for (int r = 0; r < 4; r++) {
        int i = i0 + ty*4 + r;
        float bv = bias ? bias[i] : 0.f;
#pragma unroll
        for (int c = 0; c < 4; c++) {
            int j = j0 + tx*4 + c;
            float v = acc[r][c] + bv;
            if (res) v += res[(long long)b*bC + (long long)i*ldC + j];
            if (ACT == 1) v = fmaxf(v, 0.f);
            Cb[(long long)i*ldC + j] = v;
        }
    }
}

// ---------------- big tiled fp32 GEMM (convs): 128x128, double-buffered -----
template<bool AKI, bool BKI, int ACT>
__global__ void __launch_bounds__(256, 2)
gemm128(const float* __restrict__ A, const float* __restrict__ B,
        const float* __restrict__ bias, const float* __restrict__ res,
        float* __restrict__ C,
        int KS, int NS,
        long long sAi, long long sAk, long long sBk, long long sBj,
        long long ldC, long long bA, long long bB, long long bCz)
{
    __shared__ __align__(16) float As[2][8][132];
    __shared__ __align__(16) float Bs[2][8][132];
    int bz = blockIdx.z;
    int b  = bz / NS;
    int s  = bz - b * NS;
    const float* Ab = A + (long long)b * bA;
    const float* Bb = B + (long long)b * bB;
    float* Cb = C + (long long)bz * bCz;
    int i0 = blockIdx.y * 128, j0 = blockIdx.x * 128;
    int kstart = s * KS;
    int tid = threadIdx.x;
    int tx = tid & 15, ty = tid >> 4;

    int akc[4], aii[4], bkc[4], bjj[4];
#pragma unroll
    for (int l = 0; l < 4; l++) {
        int t = tid + l*256;
        if (AKI) { akc[l] = t & 7; aii[l] = t >> 3; } else { aii[l] = t & 127; akc[l] = t >> 7; }
        if (BKI) { bkc[l] = t & 7; bjj[l] = t >> 3; } else { bjj[l] = t & 127; bkc[l] = t >> 7; }
    }

    float acc[8][8];
#pragma unroll
    for (int r = 0; r < 8; r++)
#pragma unroll
        for (int c = 0; c < 8; c++) acc[r][c] = 0.f;

#pragma unroll
    for (int l = 0; l < 4; l++) {
        As[0][akc[l]][aii[l]] = Ab[(long long)(i0+aii[l])*sAi + (long long)(kstart+akc[l])*sAk];
        Bs[0][bkc[l]][bjj[l]] = Bb[(long long)(kstart+bkc[l])*sBk + (long long)(j0+bjj[l])*sBj];
    }
    __syncthreads();

    int buf = 0;
    for (int k0 = 0; k0 < KS; k0 += 8) {
        bool has_next = (k0 + 8 < KS);
        float pa[4], pb[4];
        if (has_next) {
            int kb = kstart + k0 + 8;
#pragma unroll
            for (int l = 0; l < 4; l++) {
                pa[l] = Ab[(long long)(i0+aii[l])*sAi + (long long)(kb+akc[l])*sAk];
                pb[l] = Bb[(long long)(kb+bkc[l])*sBk + (long long)(j0+bjj[l])*sBj];
            }
        }
#pragma unroll
        for (int kc = 0; kc < 8; kc++) {
            float4 a0 = *(const float4*)&As[buf][kc][ty*4];
            float4 a1 = *(const float4*)&As[buf][kc][64 + ty*4];
            float4 b0 = *(const float4*)&Bs[buf][kc][tx*4];
            float4 b1 = *(const float4*)&Bs[buf][kc][64 + tx*4];
            float ar[8] = {a0.x,a0.y,a0.z,a0.w, a1.x,a1.y,a1.z,a1.w};
            float br[8] = {b0.x,b0.y,b0.z,b0.w, b1.x,b1.y,b1.z,b1.w};
#pragma unroll
            for (int r = 0; r < 8; r++)
#pragma unroll
                for (int c = 0; c < 8; c++)
                    acc[r][c] = fmaf(ar[r], br[c], acc[r][c]);
        }
        if (has_next) {
            int nb = buf ^ 1;
#pragma unroll
            for (int l = 0; l < 4; l++) {
                As[nb][akc[l]][aii[l]] = pa[l];
                Bs[nb][bkc[l]][bjj[l]] = pb[l];
            }
            __syncthreads();
            buf = nb;
        }
    }

#pragma unroll
    for (int r = 0; r < 8; r++) {
        int i = i0 + (r < 4 ? ty*4 + r : 64 + ty*4 + (r-4));
        float bv = bias ? bias[i] : 0.f;
#pragma unroll
        for (int c = 0; c < 8; c++) {
            int j = j0 + (c < 4 ? tx*4 + c : 64 + tx*4 + (c-4));
            float v = acc[r][c] + bv;
            if (res) v += res[(long long)bz*bCz + (long long)i*ldC + j];
            if (ACT == 1) v = fmaxf(v, 0.f);
            Cb[(long long)i*ldC + j] = v;
        }
    }
}

// ---------------- tensor-core GEMM (split-bf16 x3, m16n8k16 HMMA) -----------
// C[z][i][j] = sum_k A[i,k]*B[k,j], fp32 in/out, ~fp32 accuracy via hi/lo
// bf16 decomposition (hi*hi + hi*lo + lo*hi). Block tile 128x128, k-chunk 32.
// 8 warps: wi=w&3 (32 rows), wj=w>>2 (64 cols). KS%32==0, dims %128==0.
__device__ __forceinline__ void mma16816(float* c, const unsigned* a,
                                         unsigned b0, unsigned b1)
{
    asm volatile(
        "mma.sync.aligned.m16n8k16.row.col.f32.bf16.bf16.f32 "
        "{%0,%1,%2,%3},{%4,%5,%6,%7},{%8,%9},{%0,%1,%2,%3};"
        : "+f"(c[0]), "+f"(c[1]), "+f"(c[2]), "+f"(c[3])
        : "r"(a[0]), "r"(a[1]), "r"(a[2]), "r"(a[3]), "r"(b0), "r"(b1));
}

__device__ __forceinline__ void ldsm4(unsigned& r0, unsigned& r1,
                                      unsigned& r2, unsigned& r3, unsigned addr)
{
    asm volatile("ldmatrix.sync.aligned.m8n8.x4.shared.b16 {%0,%1,%2,%3},[%4];"
                 : "=r"(r0), "=r"(r1), "=r"(r2), "=r"(r3) : "r"(addr));
}

#define TCPAD 40   // bf16 elems per smem row (32 data + 8 pad; 80B stride)

template<bool AKI, bool BKI>
__global__ void __launch_bounds__(256, 2)
gemm_tc(const float* __restrict__ A, const float* __restrict__ B,
        float* __restrict__ C,
        int KS, int NS,
        long long sAi, long long sAk, long long sBk, long long sBj,
        long long ldC, long long bA, long long bB, long long bCz)
{
    __shared__ __align__(16) __nv_bfloat16 Ah[128][TCPAD];
    __shared__ __align__(16) __nv_bfloat16 Al[128][TCPAD];
    __shared__ __align__(16) __nv_bfloat16 Bh[128][TCPAD];
    __shared__ __align__(16) __nv_bfloat16 Bl[128][TCPAD];

    int bz = blockIdx.z;
    int b  = bz / NS;
    int s  = bz - b * NS;
    const float* Ab = A + (long long)b * bA;
    const float* Bb = B + (long long)b * bB;
    float* Cb = C + (long long)bz * bCz;
    int i0 = blockIdx.y * 128, j0 = blockIdx.x * 128;
    int kstart = s * KS;
    int tid  = threadIdx.x;
    int lane = tid & 31;
    int w    = tid >> 5;
    int wi   = w & 3;            // 4 warps over i: 32 rows each
    int wj   = w >> 2;           // 2 warps over j: 64 cols each
    int lg = lane >> 3, lr = lane & 7;

    float acc[2][8][4];
#pragma unroll
    for (int mt = 0; mt < 2; mt++)
#pragma unroll
        for (int nt = 0; nt < 8; nt++)
#pragma unroll
            for (int q = 0; q < 4; q++) acc[mt][nt][q] = 0.f;

    for (int k0 = 0; k0 < KS; k0 += 32) {
        int kb = kstart + k0;
        // stage A (128x32) with hi/lo split
        if (AKI) {
            int k = tid & 31, i = tid >> 5;
#pragma unroll
            for (int p = 0; p < 16; p++, i += 8) {
                float v = Ab[(long long)(i0+i)*sAi + (long long)(kb+k)*sAk];
                __nv_bfloat16 h = __float2bfloat16(v);
                Ah[i][k] = h;
                Al[i][k] = __float2bfloat16(v - __bfloat162float(h));
            }
        } else {
            int i = tid & 127, k = tid >> 7;
#pragma unroll
            for (int p = 0; p < 16; p++, k += 2) {
                float v = Ab[(long long)(i0+i)*sAi + (long long)(kb+k)*sAk];
                __nv_bfloat16 h = __float2bfloat16(v);
                Ah[i][k] = h;
                Al[i][k] = __float2bfloat16(v - __bfloat162float(h));
            }
        }
        // stage B (128x32), smem layout [j][k]
        if (BKI) {
            int k = tid & 31, j = tid >> 5;
#pragma unroll
            for (int p = 0; p < 16; p++, j += 8) {
                float v = Bb[(long long)(kb+k)*sBk + (long long)(j0+j)*sBj];
                __nv_bfloat16 h = __float2bfloat16(v);
                Bh[j][k] = h;
                Bl[j][k] = __float2bfloat16(v - __bfloat162float(h));
            }
        } else {
            int j = tid & 127, k = tid >> 7;
#pragma unroll
            for (int p = 0; p < 16; p++, k += 2) {
                float v = Bb[(long long)(kb+k)*sBk + (long long)(j0+j)*sBj];
                __nv_bfloat16 h = __float2bfloat16(v);
                Bh[j][k] = h;
                Bl[j][k] = __float2bfloat16(v - __bfloat162float(h));
            }
        }
        __syncthreads();

#pragma unroll
        for (int kt = 0; kt < 32; kt += 16) {
            unsigned ah[2][4], al[2][4];
#pragma unroll
            for (int mt = 0; mt < 2; mt++) {
                int row = wi*32 + mt*16 + (lg & 1)*8 + lr;
                int col = kt + (lg >> 1)*8;
                ldsm4(ah[mt][0], ah[mt][1], ah[mt][2], ah[mt][3],
                      (unsigned)__cvta_generic_to_shared(&Ah[row][col]));
                ldsm4(al[mt][0], al[mt][1], al[mt][2], al[mt][3],
                      (unsigned)__cvta_generic_to_shared(&Al[row][col]));
            }
#pragma unroll
            for (int nt2 = 0; nt2 < 4; nt2++) {
                int row = wj*64 + nt2*16 + (lg >> 1)*8 + lr;
                int col = kt + (lg & 1)*8;
                unsigned bh[4], bl[4];
                ldsm4(bh[0], bh[1], bh[2], bh[3],
                      (unsigned)__cvta_generic_to_shared(&Bh[row][col]));
                ldsm4(bl[0], bl[1], bl[2], bl[3],
                      (unsigned)__cvta_generic_to_shared(&Bl[row][col]));
#pragma unroll
                for (int mt = 0; mt < 2; mt++) {
                    mma16816(acc[mt][nt2*2+0], ah[mt], bh[0], bh[1]);
                    mma16816(acc[mt][nt2*2+0], ah[mt], bl[0], bl[1]);
                    mma16816(acc[mt][nt2*2+0], al[mt], bh[0], bh[1]);
                    mma16816(acc[mt][nt2*2+1], ah[mt], bh[2], bh[3]);
                    mma16816(acc[mt][nt2*2+1], ah[mt], bl[2], bl[3]);
                    mma16816(acc[mt][nt2*2+1], al[mt], bh[2], bh[3]);
                }
            }
        }
        __syncthreads();
    }

    int r0 = lane >> 2, cc = (lane & 3) * 2;
#pragma unroll
    for (int mt = 0; mt < 2; mt++) {
        int i = i0 + wi*32 + mt*16 + r0;
#pragma unroll
        for (int nt = 0; nt < 8; nt++) {
            int j = j0 + wj*64 + nt*8 + cc;
            *(float2*)&Cb[(long long)i*ldC + j] =
                make_float2(acc[mt][nt][0], acc[mt][nt][1]);
            *(float2*)&Cb[(long long)(i+8)*ldC + j] =
                make_float2(acc[mt][nt][2], acc[mt][nt][3]);
        }
    }
}

// ---------------- deterministic k-split reduction for O ----------------------
__global__ void reduce8(const float* __restrict__ part, float* __restrict__ O)
{
    int idx = blockIdx.x * 256 + threadIdx.x;
    int b   = idx >> 19;
    int off = idx & ((1 << 19) - 1);
    const float* p = part + ((long long)b * 8) * (128LL * NV) + off;
    float acc = 0.f;
#pragma unroll
    for (int s = 0; s < 8; s++) acc += p[(long long)s * 128 * NV];
    O[idx] = acc;
}

// ---------------- BN statistics (fp64, deterministic) -----------------------
__global__ void bn_stats(const float* __restrict__ y, int Co)
{
    int ch = blockIdx.x, tid = threadIdx.x;
    double s = 0.0, s2 = 0.0;
    for (int t = tid; t < NNV; t += 256) {
        int b = t >> 12, n = t & 4095;
        float v = y[((size_t)b*Co + ch)*NV + n];
        s += v; s2 += (double)v * (double)v;
    }
    __shared__ double rs[256], rq[256];
    rs[tid] = s; rq[tid] = s2; __syncthreads();
    for (int st = 128; st > 0; st >>= 1) {
        if (tid < st) { rs[tid] += rs[tid+st]; rq[tid] += rq[tid+st]; }
        __syncthreads();
    }
    if (tid == 0) {
        double m = rs[0] / (double)NNV;
        double var = rq[0] / (double)NNV - m*m;
        g_mean[ch] = (float)m;
        g_rstd[ch] = (float)(1.0 / sqrt(var + 1e-5));
    }
}

__global__ void bn_apply(float* __restrict__ y, const float* __restrict__ gm,
                         const float* __restrict__ bt, int Co)
{
    int idx = blockIdx.x * 256 + threadIdx.x;
    if (idx >= Co * NNV) return;
    int ch = (idx >> 12) % Co;
    float v = y[idx];
    v = gm[ch] * (v - g_mean[ch]) * g_rstd[ch] + bt[ch];
    y[idx] = fmaxf(v, 0.f);
}

// ---------------- row softmax over 4096 (in place) ---------------------------
__global__ void softmax_row(float* __restrict__ S)
{
    float* p = S + (size_t)blockIdx.x * 4096;
    int tid = threadIdx.x;
    float v[16];
    float mx = -3.4e38f;
#pragma unroll
    for (int l = 0; l < 16; l++) { v[l] = p[tid + l*256]; mx = fmaxf(mx, v[l]); }
    __shared__ float red[256];
    red[tid] = mx; __syncthreads();
    for (int s = 128; s > 0; s >>= 1) {
        if (tid < s) red[tid] = fmaxf(red[tid], red[tid+s]);
        __syncthreads();
    }
    mx = red[0]; __syncthreads();
    float sum = 0.f;
#pragma unroll
    for (int l = 0; l < 16; l++) { v[l] = expf(v[l] - mx); sum += v[l]; }
    red[tid] = sum; __syncthreads();
    for (int s = 128; s > 0; s >>= 1) {
        if (tid < s) red[tid] += red[tid+s];
        __syncthreads();
    }
    float inv = 1.0f / red[0];
#pragma unroll
    for (int l = 0; l < 16; l++) p[tid + l*256] = v[l] * inv;
}

// ---------------- attention-pool tail ----------------------------------------
__global__ void score_kernel(const float* __restrict__ a, const float* __restrict__ aw2,
                             const float* __restrict__ ab2, float* __restrict__ s)
{
    int t = blockIdx.x * 256 + threadIdx.x;
    int b = t >> 12, n = t & 4095;
    float acc = ab2[0];
#pragma unroll 8
    for (int c = 0; c < 64; c++) acc += aw2[c] * a[((size_t)b*64 + c)*NV + n];
    s[t] = acc;
}

__global__ void pool_kernel(const float* __restrict__ h, const float* __restrict__ w,
                            float* __restrict__ pooled)
{
    int c = blockIdx.x, b = blockIdx.y, tid = threadIdx.x;
    const float* hp = h + ((size_t)b*256 + c)*NV;
    const float* wp = w + (size_t)b*NV;
    float acc = 0.f;
    for (int n = tid; n < NV; n += 256) acc = fmaf(hp[n], wp[n], acc);
    __shared__ float red[256];
    red[tid] = acc; __syncthreads();
    for (int s = 128; s > 0; s >>= 1) {
        if (tid < s) red[tid] += red[tid+s];
        __syncthreads();
    }
    if (tid == 0) pooled[b*256 + c] = red[0];
}

__global__ void fc_kernel(const float* __restrict__ pooled, const float* __restrict__ fcw,
                          const float* __restrict__ fcb, float* __restrict__ out)
{
    int b = blockIdx.x, j = threadIdx.x;
    __shared__ float sp[256];
    sp[j] = pooled[b*256 + j]; __syncthreads();
    float acc = fcb[j];
#pragma unroll 8
    for (int c = 0; c < 256; c++) acc = fmaf(sp[c], fcw[j*256 + c], acc);
    out[b*256 + j] = fmaxf(acc, 0.f);
}

// ---------------- host launch ------------------------------------------------
static float* sym_addr(const void* s)
{
    void* p = nullptr;
    cudaGetSymbolAddress(&p, s);
    return (float*)p;
}

extern "C" void kernel_launch(void* const* d_in, const int* in_sizes, int n_in,
                              void* d_out, int out_size)
{
    const float* x   = (const float*)d_in[0];
    const float* w1  = (const float*)d_in[1];
    const float* b1  = (const float*)d_in[2];
    const float* g1  = (const float*)d_in[3];
    const float* be1 = (const float*)d_in[4];
    const float* w2  = (const float*)d_in[5];
    const float* b2  = (const float*)d_in[6];
    const float* g2  = (const float*)d_in[7];
    const float* be2 = (const float*)d_in[8];
    const float* w3  = (const float*)d_in[9];
    const float* b3  = (const float*)d_in[10];
    const float* g3  = (const float*)d_in[11];
    const float* be3 = (const float*)d_in[12];
    const float* qw  = (const float*)d_in[13];
    const float* qb  = (const float*)d_in[14];
    const float* kw  = (const float*)d_in[15];
    const float* kb  = (const float*)d_in[16];
    const float* vw  = (const float*)d_in[17];
    const float* vb  = (const float*)d_in[18];
    const float* fw  = (const float*)d_in[19];
    const float* fb  = (const float*)d_in[20];
    const float* aw1 = (const float*)d_in[21];
    const float* ab1 = (const float*)d_in[22];
    const float* aw2 = (const float*)d_in[23];
    const float* ab2 = (const float*)d_in[24];
    const float* fcw = (const float*)d_in[25];
    const float* fcb = (const float*)d_in[26];
    float* out = (float*)d_out;

    float* h18 = sym_addr(g_h18);
    float* x1  = sym_addr(g_x1);
    float* x2  = sym_addr(g_x2);
    float* h3  = sym_addr(g_h3);
    float* Qp  = sym_addr(g_Q);
    float* Kp  = sym_addr(g_Kt);
    float* Vp  = sym_addr(g_V);
    float* Op  = sym_addr(g_O);
    float* Sp  = sym_addr(g_S);
    float* P8  = sym_addr(g_P8);
    float* h4  = sym_addr(g_h4);
    float* ap  = sym_addr(g_a);
    float* sp  = sym_addr(g_sc);
    float* pp  = sym_addr(g_pooled);

    const long long N = NV;

    // 1) KNN + local diff features
    knn_kernel<<<dim3(16, 4), 256>>>(x);

    // 2) conv1 (18->64) + BN + ReLU
    gemm_k<false,false,0><<<dim3(64,1,4),256>>>(w1, h18, b1, nullptr, x1,
        64, 18, 18,1, N,1, N, 0, 18*N, 64*N);
    bn_stats<<<64,256>>>(x1, 64);
    bn_apply<<<(64*NNV+255)/256,256>>>(x1, g1, be1, 64);

    // 3) conv2 (64->128)
    gemm128<true,false,0><<<dim3(32,1,4),256>>>(w2, x1, b2, nullptr, x2,
        64, 1, 64,1, N,1, N, 0, 64*N, 128*N);
    bn_stats<<<128,256>>>(x2, 128);
    bn_apply<<<(128*NNV+255)/256,256>>>(x2, g2, be2, 128);

    // 4) conv3 (128->256)
    gemm128<true,false,0><<<dim3(32,2,4),256>>>(w3, x2, b3, nullptr, h3,
        128, 1, 128,1, N,1, N, 0, 128*N, 256*N);
    bn_stats<<<256,256>>>(h3, 256);
    bn_apply<<<(256*NNV+255)/256,256>>>(h3, g3, be3, 256);

    // 5) Q, K, V projections (256->128)
    gemm128<true,false,0><<<dim3(32,1,4),256>>>(qw, h3, qb, nullptr, Qp,
        256, 1, 256,1, N,1, N, 0, 256*N, 128*N);
    gemm128<true,false,0><<<dim3(32,1,4),256>>>(kw, h3, kb, nullptr, Kp,
        256, 1, 256,1, N,1, N, 0, 256*N, 128*N);
    gemm128<true,false,0><<<dim3(32,1,4),256>>>(vw, h3, vb, nullptr, Vp,
        256, 1, 256,1, N,1, N, 0, 256*N, 128*N);

    // 6) S = Q^T K via tensor cores (split-bf16 x3)
    gemm_tc<false,false><<<dim3(32,32,4),256>>>(Qp, Kp, Sp,
        128, 1, 1,N, N,1, N, 128*N, 128*N, (long long)N*N);

    // 7) softmax over m
    softmax_row<<<16384,256>>>(Sp);

    // 8) O = V · P^T via tensor cores, k-split x8 + deterministic reduce
    gemm_tc<true,true><<<dim3(32,1,32),256>>>(Vp, Sp, P8,
        512, 8, N,1, 1,N, N, 128*N, (long long)N*N, 128*N);
    reduce8<<<(BV*128*NV)/256, 256>>>(P8, Op);

    // 9) h4 = conv(O, fw) + fb + h3 (residual)
    gemm128<true,false,0><<<dim3(32,2,4),256>>>(fw, Op, fb, h3, h4,
        128, 1, 128,1, N,1, N, 0, 128*N, 256*N);

    // 10) a = relu(conv(h4, aw1))
    gemm_k<false,false,1><<<dim3(64,1,4),256>>>(aw1, h4, ab1, nullptr, ap,
        64, 256, 256,1, N,1, N, 0, 256*N, 64*N);

    // 11) scores, softmax over n, weighted pool, final FC
    score_kernel<<<64,256>>>(ap, aw2, ab2, sp);
    softmax_row<<<4,256>>>(sp);
    pool_kernel<<<dim3(256,4),256>>>(h4, sp, pp);
    fc_kernel<<<4,256>>>(pp, fcw, fcb, out);
}

// round 10
// speedup vs baseline: 1.4422x; 1.0749x over previous
#include <cuda_runtime.h>
#include <cuda_bf16.h>
#include <math.h>

#define BV 4
#define NV 4096
#define NNV (BV*NV)

// ---------------- scratch (device globals; no allocation allowed) ----------
__device__ float g_h18[(size_t)BV*18*NV];
__device__ float g_x1 [(size_t)BV*64*NV];
__device__ float g_x2 [(size_t)BV*128*NV];
__device__ float g_h3 [(size_t)BV*256*NV];
__device__ float g_Q  [(size_t)BV*128*NV];
__device__ float g_Kt [(size_t)BV*128*NV];
__device__ float g_V  [(size_t)BV*128*NV];
__device__ float g_O  [(size_t)BV*128*NV];
__device__ float g_S  [(size_t)BV*NV*NV];      // 268 MB attention matrix
__device__ float g_P8 [(size_t)BV*8*128*NV];   // 64 MB k-split partials for O
__device__ float g_h4 [(size_t)BV*256*NV];
__device__ float g_a  [(size_t)BV*64*NV];
__device__ float g_sc [(size_t)BV*NV];
__device__ float g_mean[256];
__device__ float g_rstd[256];
__device__ float g_pooled[BV*256];

// ---------------- KNN + local diffs ----------------------------------------
__global__ void knn_kernel(const float* __restrict__ x)
{
    __shared__ float sx[NV], sy[NV], sz[NV];
    int b = blockIdx.y;
    const float* xb = x + (size_t)b * NV * 9;
    for (int m = threadIdx.x; m < NV; m += blockDim.x) {
        sx[m] = xb[(size_t)m*9 + 0];
        sy[m] = xb[(size_t)m*9 + 1];
        sz[m] = xb[(size_t)m*9 + 2];
    }
    __syncthreads();

    int n = blockIdx.x * blockDim.x + threadIdx.x;
    float qx = sx[n], qy = sy[n], qz = sz[n];
    float qs = fmaf(qz, qz, fmaf(qy, qy, qx*qx));

    float bd[9]; int bi[9];
#pragma unroll
    for (int j = 0; j < 9; j++) { bd[j] = 3.4e38f; bi[j] = 0; }

#pragma unroll 4
    for (int m = 0; m < NV; m++) {
        float mx = sx[m], my = sy[m], mz = sz[m];
        float ms  = fmaf(mz, mz, fmaf(my, my, mx*mx));
        float dot = fmaf(mz, qz, fmaf(my, qy, mx*qx));
        float d2  = fmaf(-2.f, dot, qs + ms);
        d2 = fmaxf(d2, 0.f);
        if (d2 < bd[8]) {
            bool pl = false;
#pragma unroll
            for (int j = 8; j >= 1; j--) {
                if (!pl) {
                    if (d2 < bd[j-1]) { bd[j] = bd[j-1]; bi[j] = bi[j-1]; }
                    else              { bd[j] = d2;      bi[j] = m; pl = true; }
                }
            }
            if (!pl) { bd[0] = d2; bi[0] = m; }
        }
    }

    float acc[9];
#pragma unroll
    for (int c = 0; c < 9; c++) acc[c] = 0.f;
#pragma unroll
    for (int j = 1; j < 9; j++) {
        const float* xr = xb + (size_t)bi[j] * 9;
#pragma unroll
        for (int c = 0; c < 9; c++) acc[c] += xr[c];
    }
    const float* xn = xb + (size_t)n * 9;
#pragma unroll
    for (int c = 0; c < 9; c++) {
        float xc = xn[c];
        g_h18[((size_t)b*18 + c    )*NV + n] = acc[c]*0.125f - xc;
        g_h18[((size_t)b*18 + 9 + c)*NV + n] = xc;
    }
}

// ---------------- generic tiled GEMM (64x64, small/odd shapes) --------------
template<bool AKI, bool BKI, int ACT>
__global__ void __launch_bounds__(256)
gemm_k(const float* __restrict__ A, const float* __restrict__ B,
       const float* __restrict__ bias, const float* __restrict__ res,
       float* __restrict__ C,
       int M, int K,
       long long sAi, long long sAk, long long sBk, long long sBj,
       long long ldC, long long bA, long long bB, long long bC)
{
    __shared__ __align__(16) float As[16*66];
    __shared__ __align__(16) float Bs[16*66];
    int b  = blockIdx.z;
    const float* Ab = A + (long long)b * bA;
    const float* Bb = B + (long long)b * bB;
    float* Cb = C + (long long)b * bC;
    int i0 = blockIdx.y * 64, j0 = blockIdx.x * 64;
    int tid = threadIdx.x;
    int tx = tid & 15, ty = tid >> 4;

    float acc[4][4];
#pragma unroll
    for (int r = 0; r < 4; r++)
#pragma unroll
        for (int c = 0; c < 4; c++) acc[r][c] = 0.f;

    for (int k0 = 0; k0 < K; k0 += 16) {
#pragma unroll
        for (int l = 0; l < 4; l++) {
            int t = tid + l*256;
            int kc, ii;
            if (AKI) { ii = t >> 4; kc = t & 15; } else { kc = t >> 6; ii = t & 63; }
            float av = 0.f;
            if (k0 + kc < K) av = Ab[(long long)(i0+ii)*sAi + (long long)(k0+kc)*sAk];
            As[kc*66 + ii] = av;
            int jj;
            if (BKI) { jj = t >> 4; kc = t & 15; } else { kc = t >> 6; jj = t & 63; }
            float bv = 0.f;
            if (k0 + kc < K) bv = Bb[(long long)(k0+kc)*sBk + (long long)(j0+jj)*sBj];
            Bs[kc*66 + jj] = bv;
        }
        __syncthreads();
#pragma unroll
        for (int kc = 0; kc < 16; kc++) {
            float2 a0 = *(const float2*)&As[kc*66 + ty*4];
            float2 a1 = *(const float2*)&As[kc*66 + ty*4 + 2];
            float2 b0 = *(const float2*)&Bs[kc*66 + tx*4];
            float2 b1 = *(const float2*)&Bs[kc*66 + tx*4 + 2];
            float ar[4] = {a0.x, a0.y, a1.x, a1.y};
            float br[4] = {b0.x, b0.y, b1.x, b1.y};
#pragma unroll
            for (int r = 0; r < 4; r++)
#pragma unroll
                for (int c = 0; c < 4; c++)
                    acc[r][c] = fmaf(ar[r], br[c], acc[r][c]);
        }
        __syncthreads();
    }

#pragma unroll
    for (int r = 0; r < 4; r++) {
        int i = i0 + ty*4 + r;
        float bv = bias ? bias[i] : 0.f;
#pragma unroll
        for (int c = 0; c < 4; c++) {
            int j = j0 + tx*4 + c;
            float v = acc[r][c] + bv;
            if (res) v += res[(long long)b*bC + (long long)i*ldC + j];
            if (ACT == 1) v = fmaxf(v, 0.f);
            Cb[(long long)i*ldC + j] = v;
        }
    }
}

// ---------------- tensor-core GEMM (split-bf16 x3, m16n8k16 HMMA) -----------
// C[z][i][j] = sum_k A[i,k]*B[k,j] (+bias[i] +res, opt ReLU), fp32 in/out,
// ~fp32 accuracy via hi/lo bf16 decomposition (hi*hi + hi*lo + lo*hi).
// Block tile 128x128, k-chunk 32. 8 warps: wi=w&3 (32 rows), wj=w>>2 (64 cols).
// KS%32==0, dims %128==0.
__device__ __forceinline__ void mma16816(float* c, const unsigned* a,
                                         unsigned b0, unsigned b1)
{
    asm volatile(
        "mma.sync.aligned.m16n8k16.row.col.f32.bf16.bf16.f32 "
        "{%0,%1,%2,%3},{%4,%5,%6,%7},{%8,%9},{%0,%1,%2,%3};"
        : "+f"(c[0]), "+f"(c[1]), "+f"(c[2]), "+f"(c[3])
        : "r"(a[0]), "r"(a[1]), "r"(a[2]), "r"(a[3]), "r"(b0), "r"(b1));
}

__device__ __forceinline__ void ldsm4(unsigned& r0, unsigned& r1,
                                      unsigned& r2, unsigned& r3, unsigned addr)
{
    asm volatile("ldmatrix.sync.aligned.m8n8.x4.shared.b16 {%0,%1,%2,%3},[%4];"
                 : "=r"(r0), "=r"(r1), "=r"(r2), "=r"(r3) : "r"(addr));
}

#define TCPAD 40   // bf16 elems per smem row (32 data + 8 pad; 80B stride)

template<bool AKI, bool BKI, int ACT>
__global__ void __launch_bounds__(256, 2)
gemm_tc(const float* __restrict__ A, const float* __restrict__ B,
        const float* __restrict__ bias, const float* __restrict__ res,
        float* __restrict__ C,
        int KS, int NS,
        long long sAi, long long sAk, long long sBk, long long sBj,
        long long ldC, long long bA, long long bB, long long bCz)
{
    __shared__ __align__(16) __nv_bfloat16 Ah[128][TCPAD];
    __shared__ __align__(16) __nv_bfloat16 Al[128][TCPAD];
    __shared__ __align__(16) __nv_bfloat16 Bh[128][TCPAD];
    __shared__ __align__(16) __nv_bfloat16 Bl[128][TCPAD];

    int bz = blockIdx.z;
    int b  = bz / NS;
    int s  = bz - b * NS;
    const float* Ab = A + (long long)b * bA;
    const float* Bb = B + (long long)b * bB;
    float* Cb = C + (long long)bz * bCz;
    int i0 = blockIdx.y * 128, j0 = blockIdx.x * 128;
    int kstart = s * KS;
    int tid  = threadIdx.x;
    int lane = tid & 31;
    int w    = tid >> 5;
    int wi   = w & 3;            // 4 warps over i: 32 rows each
    int wj   = w >> 2;           // 2 warps over j: 64 cols each
    int lg = lane >> 3, lr = lane & 7;

    float acc[2][8][4];
#pragma unroll
    for (int mt = 0; mt < 2; mt++)
#pragma unroll
        for (int nt = 0; nt < 8; nt++)
#pragma unroll
            for (int q = 0; q < 4; q++) acc[mt][nt][q] = 0.f;

    for (int k0 = 0; k0 < KS; k0 += 32) {
        int kb = kstart + k0;
        // stage A (128x32) with hi/lo split
        if (AKI) {
            int k = tid & 31, i = tid >> 5;
#pragma unroll
            for (int p = 0; p < 16; p++, i += 8) {
                float v = Ab[(long long)(i0+i)*sAi + (long long)(kb+k)*sAk];
                __nv_bfloat16 h = __float2bfloat16(v);
                Ah[i][k] = h;
                Al[i][k] = __float2bfloat16(v - __bfloat162float(h));
            }
        } else {
            int i = tid & 127, k = tid >> 7;
#pragma unroll
            for (int p = 0; p < 16; p++, k += 2) {
                float v = Ab[(long long)(i0+i)*sAi + (long long)(kb+k)*sAk];
                __nv_bfloat16 h = __float2bfloat16(v);
                Ah[i][k] = h;
                Al[i][k] = __float2bfloat16(v - __bfloat162float(h));
            }
        }
        // stage B (128x32), smem layout [j][k]
        if (BKI) {
            int k = tid & 31, j = tid >> 5;
#pragma unroll
            for (int p = 0; p < 16; p++, j += 8) {
                float v = Bb[(long long)(kb+k)*sBk + (long long)(j0+j)*sBj];
                __nv_bfloat16 h = __float2bfloat16(v);
                Bh[j][k] = h;
                Bl[j][k] = __float2bfloat16(v - __bfloat162float(h));
            }
        } else {
            int j = tid & 127, k = tid >> 7;
#pragma unroll
            for (int p = 0; p < 16; p++, k += 2) {
                float v = Bb[(long long)(kb+k)*sBk + (long long)(j0+j)*sBj];
                __nv_bfloat16 h = __float2bfloat16(v);
                Bh[j][k] = h;
                Bl[j][k] = __float2bfloat16(v - __bfloat162float(h));
            }
        }
        __syncthreads();

#pragma unroll
        for (int kt = 0; kt < 32; kt += 16) {
            unsigned ah[2][4], al[2][4];
#pragma unroll
            for (int mt = 0; mt < 2; mt++) {
                int row = wi*32 + mt*16 + (lg & 1)*8 + lr;
                int col = kt + (lg >> 1)*8;
                ldsm4(ah[mt][0], ah[mt][1], ah[mt][2], ah[mt][3],
                      (unsigned)__cvta_generic_to_shared(&Ah[row][col]));
                ldsm4(al[mt][0], al[mt][1], al[mt][2], al[mt][3],
                      (unsigned)__cvta_generic_to_shared(&Al[row][col]));
            }
#pragma unroll
            for (int nt2 = 0; nt2 < 4; nt2++) {
                int row = wj*64 + nt2*16 + (lg >> 1)*8 + lr;
                int col = kt + (lg & 1)*8;
                unsigned bh[4], bl[4];
                ldsm4(bh[0], bh[1], bh[2], bh[3],
                      (unsigned)__cvta_generic_to_shared(&Bh[row][col]));
                ldsm4(bl[0], bl[1], bl[2], bl[3],
                      (unsigned)__cvta_generic_to_shared(&Bl[row][col]));
#pragma unroll
                for (int mt = 0; mt < 2; mt++) {
                    mma16816(acc[mt][nt2*2+0], ah[mt], bh[0], bh[1]);
                    mma16816(acc[mt][nt2*2+0], ah[mt], bl[0], bl[1]);
                    mma16816(acc[mt][nt2*2+0], al[mt], bh[0], bh[1]);
                    mma16816(acc[mt][nt2*2+1], ah[mt], bh[2], bh[3]);
                    mma16816(acc[mt][nt2*2+1], ah[mt], bl[2], bl[3]);
                    mma16816(acc[mt][nt2*2+1], al[mt], bh[2], bh[3]);
                }
            }
        }
        __syncthreads();
    }

    // epilogue: bias / residual / ReLU (mirrors gemm128 semantics)
    int r0 = lane >> 2, cc = (lane & 3) * 2;
#pragma unroll
    for (int mt = 0; mt < 2; mt++) {
        int i = i0 + wi*32 + mt*16 + r0;
        float bv0 = bias ? bias[i]     : 0.f;
        float bv1 = bias ? bias[i + 8] : 0.f;
#pragma unroll
        for (int nt = 0; nt < 8; nt++) {
            int j = j0 + wj*64 + nt*8 + cc;
            float v0 = acc[mt][nt][0] + bv0;
            float v1 = acc[mt][nt][1] + bv0;
            float v2 = acc[mt][nt][2] + bv1;
            float v3 = acc[mt][nt][3] + bv1;
            if (res) {
                const float* rp = res + (long long)bz*bCz;
                v0 += rp[(long long)i*ldC + j];
                v1 += rp[(long long)i*ldC + j + 1];
                v2 += rp[(long long)(i+8)*ldC + j];
                v3 += rp[(long long)(i+8)*ldC + j + 1];
            }
            if (ACT == 1) {
                v0 = fmaxf(v0, 0.f); v1 = fmaxf(v1, 0.f);
                v2 = fmaxf(v2, 0.f); v3 = fmaxf(v3, 0.f);
            }
            *(float2*)&Cb[(long long)i*ldC + j]     = make_float2(v0, v1);
            *(float2*)&Cb[(long long)(i+8)*ldC + j] = make_float2(v2, v3);
        }
    }
}

// ---------------- deterministic k-split reduction for O ----------------------
__global__ void reduce8(const float* __restrict__ part, float* __restrict__ O)
{
    int idx = blockIdx.x * 256 + threadIdx.x;
    int b   = idx >> 19;
    int off = idx & ((1 << 19) - 1);
    const float* p = part + ((long long)b * 8) * (128LL * NV) + off;
    float acc = 0.f;
#pragma unroll
    for (int s = 0; s < 8; s++) acc += p[(long long)s * 128 * NV];
    O[idx] = acc;
}

// ---------------- BN statistics (fp64, deterministic) -----------------------
__global__ void bn_stats(const float* __restrict__ y, int Co)
{
    int ch = blockIdx.x, tid = threadIdx.x;
    double s = 0.0, s2 = 0.0;
    for (int t = tid; t < NNV; t += 256) {
        int b = t >> 12, n = t & 4095;
        float v = y[((size_t)b*Co + ch)*NV + n];
        s += v; s2 += (double)v * (double)v;
    }
    __shared__ double rs[256], rq[256];
    rs[tid] = s; rq[tid] = s2; __syncthreads();
    for (int st = 128; st > 0; st >>= 1) {
        if (tid < st) { rs[tid] += rs[tid+st]; rq[tid] += rq[tid+st]; }
        __syncthreads();
    }
    if (tid == 0) {
        double m = rs[0] / (double)NNV;
        double var = rq[0] / (double)NNV - m*m;
        g_mean[ch] = (float)m;
        g_rstd[ch] = (float)(1.0 / sqrt(var + 1e-5));
    }
}

__global__ void bn_apply(float* __restrict__ y, const float* __restrict__ gm,
                         const float* __restrict__ bt, int Co)
{
    int idx = blockIdx.x * 256 + threadIdx.x;
    if (idx >= Co * NNV) return;
    int ch = (idx >> 12) % Co;
    float v = y[idx];
    v = gm[ch] * (v - g_mean[ch]) * g_rstd[ch] + bt[ch];
    y[idx] = fmaxf(v, 0.f);
}

// ---------------- row softmax over 4096 (in place) ---------------------------
__global__ void softmax_row(float* __restrict__ S)
{
    float* p = S + (size_t)blockIdx.x * 4096;
    int tid = threadIdx.x;
    float v[16];
    float mx = -3.4e38f;
#pragma unroll
    for (int l = 0; l < 16; l++) { v[l] = p[tid + l*256]; mx = fmaxf(mx, v[l]); }
    __shared__ float red[256];
    red[tid] = mx; __syncthreads();
    for (int s = 128; s > 0; s >>= 1) {
        if (tid < s) red[tid] = fmaxf(red[tid], red[tid+s]);
        __syncthreads();
    }
    mx = red[0]; __syncthreads();
    float sum = 0.f;
#pragma unroll
    for (int l = 0; l < 16; l++) { v[l] = expf(v[l] - mx); sum += v[l]; }
    red[tid] = sum; __syncthreads();
    for (int s = 128; s > 0; s >>= 1) {
        if (tid < s) red[tid] += red[tid+s];
        __syncthreads();
    }
    float inv = 1.0f / red[0];
#pragma unroll
    for (int l = 0; l < 16; l++) p[tid + l*256] = v[l] * inv;
}

// ---------------- attention-pool tail ----------------------------------------
__global__ void score_kernel(const float* __restrict__ a, const float* __restrict__ aw2,
                             const float* __restrict__ ab2, float* __restrict__ s)
{
    int t = blockIdx.x * 256 + threadIdx.x;
    int b = t >> 12, n = t & 4095;
    float acc = ab2[0];
#pragma unroll 8
    for (int c = 0; c < 64; c++) acc += aw2[c] * a[((size_t)b*64 + c)*NV + n];
    s[t] = acc;
}

__global__ void pool_kernel(const float* __restrict__ h, const float* __restrict__ w,
                            float* __restrict__ pooled)
{
    int c = blockIdx.x, b = blockIdx.y, tid = threadIdx.x;
    const float* hp = h + ((size_t)b*256 + c)*NV;
    const float* wp = w + (size_t)b*NV;
    float acc = 0.f;
    for (int n = tid; n < NV; n += 256) acc = fmaf(hp[n], wp[n], acc);
    __shared__ float red[256];
    red[tid] = acc; __syncthreads();
    for (int s = 128; s > 0; s >>= 1) {
        if (tid < s) red[tid] += red[tid+s];
        __syncthreads();
    }
    if (tid == 0) pooled[b*256 + c] = red[0];
}

__global__ void fc_kernel(const float* __restrict__ pooled, const float* __restrict__ fcw,
                          const float* __restrict__ fcb, float* __restrict__ out)
{
    int b = blockIdx.x, j = threadIdx.x;
    __shared__ float sp[256];
    sp[j] = pooled[b*256 + j]; __syncthreads();
    float acc = fcb[j];
#pragma unroll 8
    for (int c = 0; c < 256; c++) acc = fmaf(sp[c], fcw[j*256 + c], acc);
    out[b*256 + j] = fmaxf(acc, 0.f);
}

// ---------------- host launch ------------------------------------------------
static float* sym_addr(const void* s)
{
    void* p = nullptr;
    cudaGetSymbolAddress(&p, s);
    return (float*)p;
}

extern "C" void kernel_launch(void* const* d_in, const int* in_sizes, int n_in,
                              void* d_out, int out_size)
{
    const float* x   = (const float*)d_in[0];
    const float* w1  = (const float*)d_in[1];
    const float* b1  = (const float*)d_in[2];
    const float* g1  = (const float*)d_in[3];
    const float* be1 = (const float*)d_in[4];
    const float* w2  = (const float*)d_in[5];
    const float* b2  = (const float*)d_in[6];
    const float* g2  = (const float*)d_in[7];
    const float* be2 = (const float*)d_in[8];
    const float* w3  = (const float*)d_in[9];
    const float* b3  = (const float*)d_in[10];
    const float* g3  = (const float*)d_in[11];
    const float* be3 = (const float*)d_in[12];
    const float* qw  = (const float*)d_in[13];
    const float* qb  = (const float*)d_in[14];
    const float* kw  = (const float*)d_in[15];
    const float* kb  = (const float*)d_in[16];
    const float* vw  = (const float*)d_in[17];
    const float* vb  = (const float*)d_in[18];
    const float* fw  = (const float*)d_in[19];
    const float* fb  = (const float*)d_in[20];
    const float* aw1 = (const float*)d_in[21];
    const float* ab1 = (const float*)d_in[22];
    const float* aw2 = (const float*)d_in[23];
    const float* ab2 = (const float*)d_in[24];
    const float* fcw = (const float*)d_in[25];
    const float* fcb = (const float*)d_in[26];
    float* out = (float*)d_out;

    float* h18 = sym_addr(g_h18);
    float* x1  = sym_addr(g_x1);
    float* x2  = sym_addr(g_x2);
    float* h3  = sym_addr(g_h3);
    float* Qp  = sym_addr(g_Q);
    float* Kp  = sym_addr(g_Kt);
    float* Vp  = sym_addr(g_V);
    float* Op  = sym_addr(g_O);
    float* Sp  = sym_addr(g_S);
    float* P8  = sym_addr(g_P8);
    float* h4  = sym_addr(g_h4);
    float* ap  = sym_addr(g_a);
    float* sp  = sym_addr(g_sc);
    float* pp  = sym_addr(g_pooled);

    const long long N = NV;

    // 1) KNN + local diff features
    knn_kernel<<<dim3(16, 4), 256>>>(x);

    // 2) conv1 (18->64) + BN + ReLU (K=18: stays on 64x64 fp32 kernel)
    gemm_k<false,false,0><<<dim3(64,1,4),256>>>(w1, h18, b1, nullptr, x1,
        64, 18, 18,1, N,1, N, 0, 18*N, 64*N);
    bn_stats<<<64,256>>>(x1, 64);
    bn_apply<<<(64*NNV+255)/256,256>>>(x1, g1, be1, 64);

    // 3) conv2 (64->128) on tensor cores
    gemm_tc<true,false,0><<<dim3(32,1,4),256>>>(w2, x1, b2, nullptr, x2,
        64, 1, 64,1, N,1, N, 0, 64*N, 128*N);
    bn_stats<<<128,256>>>(x2, 128);
    bn_apply<<<(128*NNV+255)/256,256>>>(x2, g2, be2, 128);

    // 4) conv3 (128->256) on tensor cores
    gemm_tc<true,false,0><<<dim3(32,2,4),256>>>(w3, x2, b3, nullptr, h3,
        128, 1, 128,1, N,1, N, 0, 128*N, 256*N);
    bn_stats<<<256,256>>>(h3, 256);
    bn_apply<<<(256*NNV+255)/256,256>>>(h3, g3, be3, 256);

    // 5) Q, K, V projections (256->128) on tensor cores
    gemm_tc<true,false,0><<<dim3(32,1,4),256>>>(qw, h3, qb, nullptr, Qp,
        256, 1, 256,1, N,1, N, 0, 256*N, 128*N);
    gemm_tc<true,false,0><<<dim3(32,1,4),256>>>(kw, h3, kb, nullptr, Kp,
        256, 1, 256,1, N,1, N, 0, 256*N, 128*N);
    gemm_tc<true,false,0><<<dim3(32,1,4),256>>>(vw, h3, vb, nullptr, Vp,
        256, 1, 256,1, N,1, N, 0, 256*N, 128*N);

    // 6) S = Q^T K via tensor cores
    gemm_tc<false,false,0><<<dim3(32,32,4),256>>>(Qp, Kp, nullptr, nullptr, Sp,
        128, 1, 1,N, N,1, N, 128*N, 128*N, (long long)N*N);

    // 7) softmax over m
    softmax_row<<<16384,256>>>(Sp);

    // 8) O = V · P^T via tensor cores, k-split x8 + deterministic reduce
    gemm_tc<true,true,0><<<dim3(32,1,32),256>>>(Vp, Sp, nullptr, nullptr, P8,
        512, 8, N,1, 1,N, N, 128*N, (long long)N*N, 128*N);
    reduce8<<<(BV*128*NV)/256, 256>>>(P8, Op);

    // 9) h4 = conv(O, fw) + fb + h3 (residual) on tensor cores
    gemm_tc<true,false,0><<<dim3(32,2,4),256>>>(fw, Op, fb, h3, h4,
        128, 1, 128,1, N,1, N, 0, 128*N, 256*N);

    // 10) a = relu(conv(h4, aw1))  (M=64: stays on 64x64 fp32 kernel)
    gemm_k<false,false,1><<<dim3(64,1,4),256>>>(aw1, h4, ab1, nullptr, ap,
        64, 256, 256,1, N,1, N, 0, 256*N, 64*N);

    // 11) scores, softmax over n, weighted pool, final FC
    score_kernel<<<64,256>>>(ap, aw2, ab2, sp);
    softmax_row<<<4,256>>>(sp);
    pool_kernel<<<dim3(256,4),256>>>(h4, sp, pp);
    fc_kernel<<<4,256>>>(pp, fcw, fcb, out);
}

// round 13
// speedup vs baseline: 1.5301x; 1.0609x over previous
#include <cuda_runtime.h>
#include <cuda_bf16.h>
#include <math.h>

#define BV 4
#define NV 4096
#define NNV (BV*NV)

// ---------------- scratch (device globals; no allocation allowed) ----------
__device__ float g_h18[(size_t)BV*18*NV];
__device__ float g_x1 [(size_t)BV*64*NV];
__device__ float g_x2 [(size_t)BV*128*NV];
__device__ float g_h3 [(size_t)BV*256*NV];
__device__ float g_Q  [(size_t)BV*128*NV];
__device__ float g_Kt [(size_t)BV*128*NV];
__device__ float g_V  [(size_t)BV*128*NV];
__device__ float g_O  [(size_t)BV*128*NV];
__device__ float g_S  [(size_t)BV*NV*NV];      // 268 MB attention matrix
__device__ float g_P8 [(size_t)BV*8*128*NV];   // 64 MB k-split partials for O
__device__ float g_h4 [(size_t)BV*256*NV];
__device__ float g_a  [(size_t)BV*64*NV];
__device__ float g_sc [(size_t)BV*NV];
__device__ float g_mean[256];
__device__ float g_rstd[256];
__device__ float g_pooled[BV*256];

// ---------------- KNN + local diffs ----------------------------------------
__global__ void knn_kernel(const float* __restrict__ x)
{
    __shared__ float sx[NV], sy[NV], sz[NV];
    int b = blockIdx.y;
    const float* xb = x + (size_t)b * NV * 9;
    for (int m = threadIdx.x; m < NV; m += blockDim.x) {
        sx[m] = xb[(size_t)m*9 + 0];
        sy[m] = xb[(size_t)m*9 + 1];
        sz[m] = xb[(size_t)m*9 + 2];
    }
    __syncthreads();

    int n = blockIdx.x * blockDim.x + threadIdx.x;
    float qx = sx[n], qy = sy[n], qz = sz[n];
    float qs = fmaf(qz, qz, fmaf(qy, qy, qx*qx));

    float bd[9]; int bi[9];
#pragma unroll
    for (int j = 0; j < 9; j++) { bd[j] = 3.4e38f; bi[j] = 0; }

#pragma unroll 4
    for (int m = 0; m < NV; m++) {
        float mx = sx[m], my = sy[m], mz = sz[m];
        float ms  = fmaf(mz, mz, fmaf(my, my, mx*mx));
        float dot = fmaf(mz, qz, fmaf(my, qy, mx*qx));
        float d2  = fmaf(-2.f, dot, qs + ms);
        d2 = fmaxf(d2, 0.f);
        if (d2 < bd[8]) {
            bool pl = false;
#pragma unroll
            for (int j = 8; j >= 1; j--) {
                if (!pl) {
                    if (d2 < bd[j-1]) { bd[j] = bd[j-1]; bi[j] = bi[j-1]; }
                    else              { bd[j] = d2;      bi[j] = m; pl = true; }
                }
            }
            if (!pl) { bd[0] = d2; bi[0] = m; }
        }
    }

    float acc[9];
#pragma unroll
    for (int c = 0; c < 9; c++) acc[c] = 0.f;
#pragma unroll
    for (int j = 1; j < 9; j++) {
        const float* xr = xb + (size_t)bi[j] * 9;
#pragma unroll
        for (int c = 0; c < 9; c++) acc[c] += xr[c];
    }
    const float* xn = xb + (size_t)n * 9;
#pragma unroll
    for (int c = 0; c < 9; c++) {
        float xc = xn[c];
        g_h18[((size_t)b*18 + c    )*NV + n] = acc[c]*0.125f - xc;
        g_h18[((size_t)b*18 + 9 + c)*NV + n] = xc;
    }
}

// ---------------- generic tiled GEMM (64x64, small/odd shapes) --------------
template<bool AKI, bool BKI, int ACT>
__global__ void __launch_bounds__(256)
gemm_k(const float* __restrict__ A, const float* __restrict__ B,
       const float* __restrict__ bias, const float* __restrict__ res,
       float* __restrict__ C,
       int M, int K,
       long long sAi, long long sAk, long long sBk, long long sBj,
       long long ldC, long long bA, long long bB, long long bC)
{
    __shared__ __align__(16) float As[16*66];
    __shared__ __align__(16) float Bs[16*66];
    int b  = blockIdx.z;
    const float* Ab = A + (long long)b * bA;
    const float* Bb = B + (long long)b * bB;
    float* Cb = C + (long long)b * bC;
    int i0 = blockIdx.y * 64, j0 = blockIdx.x * 64;
    int tid = threadIdx.x;
    int tx = tid & 15, ty = tid >> 4;

    float acc[4][4];
#pragma unroll
    for (int r = 0; r < 4; r++)
#pragma unroll
        for (int c = 0; c < 4; c++) acc[r][c] = 0.f;

    for (int k0 = 0; k0 < K; k0 += 16) {
#pragma unroll
        for (int l = 0; l < 4; l++) {
            int t = tid + l*256;
            int kc, ii;
            if (AKI) { ii = t >> 4; kc = t & 15; } else { kc = t >> 6; ii = t & 63; }
            float av = 0.f;
            if (k0 + kc < K) av = Ab[(long long)(i0+ii)*sAi + (long long)(k0+kc)*sAk];
            As[kc*66 + ii] = av;
            int jj;
            if (BKI) { jj = t >> 4; kc = t & 15; } else { kc = t >> 6; jj = t & 63; }
            float bv = 0.f;
            if (k0 + kc < K) bv = Bb[(long long)(k0+kc)*sBk + (long long)(j0+jj)*sBj];
            Bs[kc*66 + jj] = bv;
        }
        __syncthreads();
#pragma unroll
        for (int kc = 0; kc < 16; kc++) {
            float2 a0 = *(const float2*)&As[kc*66 + ty*4];
            float2 a1 = *(const float2*)&As[kc*66 + ty*4 + 2];
            float2 b0 = *(const float2*)&Bs[kc*66 + tx*4];
            float2 b1 = *(const float2*)&Bs[kc*66 + tx*4 + 2];
            float ar[4] = {a0.x, a0.y, a1.x, a1.y};
            float br[4] = {b0.x, b0.y, b1.x, b1.y};
#pragma unroll
            for (int r = 0; r < 4; r++)
#pragma unroll
                for (int c = 0; c < 4; c++)
                    acc[r][c] = fmaf(ar[r], br[c], acc[r][c]);
        }
        __syncthreads();
    }

#pragma unroll
    for (int r = 0; r < 4; r++) {
        int i = i0 + ty*4 + r;
        float bv = bias ? bias[i] : 0.f;
#pragma unroll
        for (int c = 0; c < 4; c++) {
            int j = j0 + tx*4 + c;
            float v = acc[r][c] + bv;
            if (res) v += res[(long long)b*bC + (long long)i*ldC + j];
            if (ACT == 1) v = fmaxf(v, 0.f);
            Cb[(long long)i*ldC + j] = v;
        }
    }
}

// ---------------- tensor-core GEMM (split-bf16 x3, m16n8k16 HMMA) -----------
// C[z][i][j] = sum_k A[i,k]*B[k,j] (+bias[i] +res, opt ReLU), fp32 in/out,
// ~fp32 accuracy via hi/lo bf16 decomposition (hi*hi + hi*lo + lo*hi).
// Block tile 128x128, k-chunk 32. 8 warps: wi=w&3 (32 rows), wj=w>>2 (64 cols).
// KS%32==0, dims %128==0.
// Contract: AKI => unit k-stride for A (sAk==1); !AKI => unit i-stride (sAi==1).
//           BKI => unit k-stride for B (sBk==1); !BKI => unit j-stride (sBj==1).
__device__ __forceinline__ void mma16816(float* c, const unsigned* a,
                                         unsigned b0, unsigned b1)
{
    asm volatile(
        "mma.sync.aligned.m16n8k16.row.col.f32.bf16.bf16.f32 "
        "{%0,%1,%2,%3},{%4,%5,%6,%7},{%8,%9},{%0,%1,%2,%3};"
        : "+f"(c[0]), "+f"(c[1]), "+f"(c[2]), "+f"(c[3])
        : "r"(a[0]), "r"(a[1]), "r"(a[2]), "r"(a[3]), "r"(b0), "r"(b1));
}

__device__ __forceinline__ void ldsm4(unsigned& r0, unsigned& r1,
                                      unsigned& r2, unsigned& r3, unsigned addr)
{
    asm volatile("ldmatrix.sync.aligned.m8n8.x4.shared.b16 {%0,%1,%2,%3},[%4];"
                 : "=r"(r0), "=r"(r1), "=r"(r2), "=r"(r3) : "r"(addr));
}

__device__ __forceinline__ unsigned pack2bf(__nv_bfloat16 a, __nv_bfloat16 b)
{
    return (unsigned)__bfloat16_as_ushort(a) |
           ((unsigned)__bfloat16_as_ushort(b) << 16);
}

#define TCPAD 40   // bf16 elems per smem row (32 data + 8 pad; 80B stride)

// Stage one 128x32 fp32 tile into hi/lo bf16 smem arrays.
// KI=true : k unit-stride in gmem -> float4 along k, STS.64.
// KI=false: row unit-stride in gmem -> 16 consecutive k per thread, STS.128.
template<bool KI>
__device__ __forceinline__ void stage_tile(
    const float* __restrict__ src, long long sRow, long long sK,
    int row0, int kb, int tid,
    __nv_bfloat16 (*Sh)[TCPAD], __nv_bfloat16 (*Sl)[TCPAD])
{
    if (KI) {
        int kg = (tid & 7) * 4;
        int rb = tid >> 3;                         // 0..31
#pragma unroll
        for (int p = 0; p < 4; p++) {
            int r = rb + p*32;
            const float4 v = *(const float4*)(src + (long long)(row0+r)*sRow + (kb+kg));
            __nv_bfloat16 h0 = __float2bfloat16(v.x), h1 = __float2bfloat16(v.y);
            __nv_bfloat16 h2 = __float2bfloat16(v.z), h3 = __float2bfloat16(v.w);
            uint2 hh = make_uint2(pack2bf(h0,h1), pack2bf(h2,h3));
            uint2 ll = make_uint2(
                pack2bf(__float2bfloat16(v.x - __bfloat162float(h0)),
                        __float2bfloat16(v.y - __bfloat162float(h1))),
                pack2bf(__float2bfloat16(v.z - __bfloat162float(h2)),
                        __float2bfloat16(v.w - __bfloat162float(h3))));
            *(uint2*)&Sh[r][kg] = hh;
            *(uint2*)&Sl[r][kg] = ll;
        }
    } else {
        int r  = tid & 127;
        int kh = (tid >> 7) * 16;                  // 0 or 16
        const float* sp = src + (long long)(row0+r) + (long long)(kb+kh)*sK;
        unsigned hw[8], lw[8];
#pragma unroll
        for (int q = 0; q < 8; q++) {
            float v0 = sp[(long long)(2*q  )*sK];
            float v1 = sp[(long long)(2*q+1)*sK];
            __nv_bfloat16 h0 = __float2bfloat16(v0), h1 = __float2bfloat16(v1);
            hw[q] = pack2bf(h0, h1);
            lw[q] = pack2bf(__float2bfloat16(v0 - __bfloat162float(h0)),
                            __float2bfloat16(v1 - __bfloat162float(h1)));
        }
        *(uint4*)&Sh[r][kh]     = make_uint4(hw[0], hw[1], hw[2], hw[3]);
        *(uint4*)&Sh[r][kh + 8] = make_uint4(hw[4], hw[5], hw[6], hw[7]);
        *(uint4*)&Sl[r][kh]     = make_uint4(lw[0], lw[1], lw[2], lw[3]);
        *(uint4*)&Sl[r][kh + 8] = make_uint4(lw[4], lw[5], lw[6], lw[7]);
    }
}

template<bool AKI, bool BKI, int ACT>
__global__ void __launch_bounds__(256, 2)
gemm_tc(const float* __restrict__ A, const float* __restrict__ B,
        const float* __restrict__ bias, const float* __restrict__ res,
        float* __restrict__ C,
        int KS, int NS,
        long long sAi, long long sAk, long long sBk, long long sBj,
        long long ldC, long long bA, long long bB, long long bCz)
{
    __shared__ __align__(16) __nv_bfloat16 Ah[128][TCPAD];
    __shared__ __align__(16) __nv_bfloat16 Al[128][TCPAD];
    __shared__ __align__(16) __nv_bfloat16 Bh[128][TCPAD];
    __shared__ __align__(16) __nv_bfloat16 Bl[128][TCPAD];

    int bz = blockIdx.z;
    int b  = bz / NS;
    int s  = bz - b * NS;
    const float* Ab = A + (long long)b * bA;
    const float* Bb = B + (long long)b * bB;
    float* Cb = C + (long long)bz * bCz;
    int i0 = blockIdx.y * 128, j0 = blockIdx.x * 128;
    int kstart = s * KS;
    int tid  = threadIdx.x;
    int lane = tid & 31;
    int w    = tid >> 5;
    int wi   = w & 3;            // 4 warps over i: 32 rows each
    int wj   = w >> 2;           // 2 warps over j: 64 cols each
    int lg = lane >> 3, lr = lane & 7;

    float acc[2][8][4];
#pragma unroll
    for (int mt = 0; mt < 2; mt++)
#pragma unroll
        for (int nt = 0; nt < 8; nt++)
#pragma unroll
            for (int q = 0; q < 4; q++) acc[mt][nt][q] = 0.f;

    for (int k0 = 0; k0 < KS; k0 += 32) {
        int kb = kstart + k0;
        // stage A (row dim = i): strides (sAi over rows, sAk over k)
        stage_tile<AKI>(Ab, sAi, sAk, i0, kb, tid, Ah, Al);
        // stage B (row dim = j): strides (sBj over rows, sBk over k)
        stage_tile<BKI>(Bb, sBj, sBk, j0, kb, tid, Bh, Bl);
        __syncthreads();

#pragma unroll
        for (int kt = 0; kt < 32; kt += 16) {
            unsigned ah[2][4], al[2][4];
#pragma unroll
            for (int mt = 0; mt < 2; mt++) {
                int row = wi*32 + mt*16 + (lg & 1)*8 + lr;
                int col = kt + (lg >> 1)*8;
                ldsm4(ah[mt][0], ah[mt][1], ah[mt][2], ah[mt][3],
                      (unsigned)__cvta_generic_to_shared(&Ah[row][col]));
                ldsm4(al[mt][0], al[mt][1], al[mt][2], al[mt][3],
                      (unsigned)__cvta_generic_to_shared(&Al[row][col]));
            }
#pragma unroll
            for (int nt2 = 0; nt2 < 4; nt2++) {
                int row = wj*64 + nt2*16 + (lg >> 1)*8 + lr;
                int col = kt + (lg & 1)*8;
                unsigned bh[4], bl[4];
                ldsm4(bh[0], bh[1], bh[2], bh[3],
                      (unsigned)__cvta_generic_to_shared(&Bh[row][col]));
                ldsm4(bl[0], bl[1], bl[2], bl[3],
                      (unsigned)__cvta_generic_to_shared(&Bl[row][col]));
#pragma unroll
                for (int mt = 0; mt < 2; mt++) {
                    mma16816(acc[mt][nt2*2+0], ah[mt], bh[0], bh[1]);
                    mma16816(acc[mt][nt2*2+0], ah[mt], bl[0], bl[1]);
                    mma16816(acc[mt][nt2*2+0], al[mt], bh[0], bh[1]);
                    mma16816(acc[mt][nt2*2+1], ah[mt], bh[2], bh[3]);
                    mma16816(acc[mt][nt2*2+1], ah[mt], bl[2], bl[3]);
                    mma16816(acc[mt][nt2*2+1], al[mt], bh[2], bh[3]);
                }
            }
        }
        __syncthreads();
    }

    // epilogue: bias / residual / ReLU
    int r0 = lane >> 2, cc = (lane & 3) * 2;
#pragma unroll
    for (int mt = 0; mt < 2; mt++) {
        int i = i0 + wi*32 + mt*16 + r0;
        float bv0 = bias ? bias[i]     : 0.f;
        float bv1 = bias ? bias[i + 8] : 0.f;
#pragma unroll
        for (int nt = 0; nt < 8; nt++) {
            int j = j0 + wj*64 + nt*8 + cc;
            float v0 = acc[mt][nt][0] + bv0;
            float v1 = acc[mt][nt][1] + bv0;
            float v2 = acc[mt][nt][2] + bv1;
            float v3 = acc[mt][nt][3] + bv1;
            if (res) {
                const float* rp = res + (long long)bz*bCz;
                v0 += rp[(long long)i*ldC + j];
                v1 += rp[(long long)i*ldC + j + 1];
                v2 += rp[(long long)(i+8)*ldC + j];
                v3 += rp[(long long)(i+8)*ldC + j + 1];
            }
            if (ACT == 1) {
                v0 = fmaxf(v0, 0.f); v1 = fmaxf(v1, 0.f);
                v2 = fmaxf(v2, 0.f); v3 = fmaxf(v3, 0.f);
            }
            *(float2*)&Cb[(long long)i*ldC + j]     = make_float2(v0, v1);
            *(float2*)&Cb[(long long)(i+8)*ldC + j] = make_float2(v2, v3);
        }
    }
}

// ---------------- deterministic k-split reduction for O ----------------------
__global__ void reduce8(const float* __restrict__ part, float* __restrict__ O)
{
    int idx = blockIdx.x * 256 + threadIdx.x;
    int b   = idx >> 19;
    int off = idx & ((1 << 19) - 1);
    const float* p = part + ((long long)b * 8) * (128LL * NV) + off;
    float acc = 0.f;
#pragma unroll
    for (int s = 0; s < 8; s++) acc += p[(long long)s * 128 * NV];
    O[idx] = acc;
}

// ---------------- BN statistics (fp64, deterministic) -----------------------
__global__ void bn_stats(const float* __restrict__ y, int Co)
{
    int ch = blockIdx.x, tid = threadIdx.x;
    double s = 0.0, s2 = 0.0;
    for (int t = tid; t < NNV; t += 256) {
        int b = t >> 12, n = t & 4095;
        float v = y[((size_t)b*Co + ch)*NV + n];
        s += v; s2 += (double)v * (double)v;
    }
    __shared__ double rs[256], rq[256];
    rs[tid] = s; rq[tid] = s2; __syncthreads();
    for (int st = 128; st > 0; st >>= 1) {
        if (tid < st) { rs[tid] += rs[tid+st]; rq[tid] += rq[tid+st]; }
        __syncthreads();
    }
    if (tid == 0) {
        double m = rs[0] / (double)NNV;
        double var = rq[0] / (double)NNV - m*m;
        g_mean[ch] = (float)m;
        g_rstd[ch] = (float)(1.0 / sqrt(var + 1e-5));
    }
}

__global__ void bn_apply(float* __restrict__ y, const float* __restrict__ gm,
                         const float* __restrict__ bt, int Co)
{
    int idx = blockIdx.x * 256 + threadIdx.x;
    if (idx >= Co * NNV) return;
    int ch = (idx >> 12) % Co;
    float v = y[idx];
    v = gm[ch] * (v - g_mean[ch]) * g_rstd[ch] + bt[ch];
    y[idx] = fmaxf(v, 0.f);
}

// ---------------- row softmax over 4096 (in place) ---------------------------
__global__ void softmax_row(float* __restrict__ S)
{
    float* p = S + (size_t)blockIdx.x * 4096;
    int tid = threadIdx.x;
    float v[16];
    float mx = -3.4e38f;
#pragma unroll
    for (int l = 0; l < 16; l++) { v[l] = p[tid + l*256]; mx = fmaxf(mx, v[l]); }
    __shared__ float red[256];
    red[tid] = mx; __syncthreads();
    for (int s = 128; s > 0; s >>= 1) {
        if (tid < s) red[tid] = fmaxf(red[tid], red[tid+s]);
        __syncthreads();
    }
    mx = red[0]; __syncthreads();
    float sum = 0.f;
#pragma unroll
    for (int l = 0; l < 16; l++) { v[l] = expf(v[l] - mx); sum += v[l]; }
    red[tid] = sum; __syncthreads();
    for (int s = 128; s > 0; s >>= 1) {
        if (tid < s) red[tid] += red[tid+s];
        __syncthreads();
    }
    float inv = 1.0f / red[0];
#pragma unroll
    for (int l = 0; l < 16; l++) p[tid + l*256] = v[l] * inv;
}

// ---------------- attention-pool tail ----------------------------------------
__global__ void score_kernel(const float* __restrict__ a, const float* __restrict__ aw2,
                             const float* __restrict__ ab2, float* __restrict__ s)
{
    int t = blockIdx.x * 256 + threadIdx.x;
    int b = t >> 12, n = t & 4095;
    float acc = ab2[0];
#pragma unroll 8
    for (int c = 0; c < 64; c++) acc += aw2[c] * a[((size_t)b*64 + c)*NV + n];
    s[t] = acc;
}

__global__ void pool_kernel(const float* __restrict__ h, const float* __restrict__ w,
                            float* __restrict__ pooled)
{
    int c = blockIdx.x, b = blockIdx.y, tid = threadIdx.x;
    const float* hp = h + ((size_t)b*256 + c)*NV;
    const float* wp = w + (size_t)b*NV;
    float acc = 0.f;
    for (int n = tid; n < NV; n += 256) acc = fmaf(hp[n], wp[n], acc);
    __shared__ float red[256];
    red[tid] = acc; __syncthreads();
    for (int s = 128; s > 0; s >>= 1) {
        if (tid < s) red[tid] += red[tid+s];
        __syncthreads();
    }
    if (tid == 0) pooled[b*256 + c] = red[0];
}

__global__ void fc_kernel(const float* __restrict__ pooled, const float* __restrict__ fcw,
                          const float* __restrict__ fcb, float* __restrict__ out)
{
    int b = blockIdx.x, j = threadIdx.x;
    __shared__ float sp[256];
    sp[j] = pooled[b*256 + j]; __syncthreads();
    float acc = fcb[j];
#pragma unroll 8
    for (int c = 0; c < 256; c++) acc = fmaf(sp[c], fcw[j*256 + c], acc);
    out[b*256 + j] = fmaxf(acc, 0.f);
}

// ---------------- host launch ------------------------------------------------
static float* sym_addr(const void* s)
{
    void* p = nullptr;
    cudaGetSymbolAddress(&p, s);
    return (float*)p;
}

extern "C" void kernel_launch(void* const* d_in, const int* in_sizes, int n_in,
                              void* d_out, int out_size)
{
    const float* x   = (const float*)d_in[0];
    const float* w1  = (const float*)d_in[1];
    const float* b1  = (const float*)d_in[2];
    const float* g1  = (const float*)d_in[3];
    const float* be1 = (const float*)d_in[4];
    const float* w2  = (const float*)d_in[5];
    const float* b2  = (const float*)d_in[6];
    const float* g2  = (const float*)d_in[7];
    const float* be2 = (const float*)d_in[8];
    const float* w3  = (const float*)d_in[9];
    const float* b3  = (const float*)d_in[10];
    const float* g3  = (const float*)d_in[11];
    const float* be3 = (const float*)d_in[12];
    const float* qw  = (const float*)d_in[13];
    const float* qb  = (const float*)d_in[14];
    const float* kw  = (const float*)d_in[15];
    const float* kb  = (const float*)d_in[16];
    const float* vw  = (const float*)d_in[17];
    const float* vb  = (const float*)d_in[18];
    const float* fw  = (const float*)d_in[19];
    const float* fb  = (const float*)d_in[20];
    const float* aw1 = (const float*)d_in[21];
    const float* ab1 = (const float*)d_in[22];
    const float* aw2 = (const float*)d_in[23];
    const float* ab2 = (const float*)d_in[24];
    const float* fcw = (const float*)d_in[25];
    const float* fcb = (const float*)d_in[26];
    float* out = (float*)d_out;

    float* h18 = sym_addr(g_h18);
    float* x1  = sym_addr(g_x1);
    float* x2  = sym_addr(g_x2);
    float* h3  = sym_addr(g_h3);
    float* Qp  = sym_addr(g_Q);
    float* Kp  = sym_addr(g_Kt);
    float* Vp  = sym_addr(g_V);
    float* Op  = sym_addr(g_O);
    float* Sp  = sym_addr(g_S);
    float* P8  = sym_addr(g_P8);
    float* h4  = sym_addr(g_h4);
    float* ap  = sym_addr(g_a);
    float* sp  = sym_addr(g_sc);
    float* pp  = sym_addr(g_pooled);

    const long long N = NV;

    // 1) KNN + local diff features
    knn_kernel<<<dim3(16, 4), 256>>>(x);

    // 2) conv1 (18->64) + BN + ReLU (K=18: stays on 64x64 fp32 kernel)
    gemm_k<false,false,0><<<dim3(64,1,4),256>>>(w1, h18, b1, nullptr, x1,
        64, 18, 18,1, N,1, N, 0, 18*N, 64*N);
    bn_stats<<<64,256>>>(x1, 64);
    bn_apply<<<(64*NNV+255)/256,256>>>(x1, g1, be1, 64);

    // 3) conv2 (64->128) on tensor cores
    gemm_tc<true,false,0><<<dim3(32,1,4),256>>>(w2, x1, b2, nullptr, x2,
        64, 1, 64,1, N,1, N, 0, 64*N, 128*N);
    bn_stats<<<128,256>>>(x2, 128);
    bn_apply<<<(128*NNV+255)/256,256>>>(x2, g2, be2, 128);

    // 4) conv3 (128->256) on tensor cores
    gemm_tc<true,false,0><<<dim3(32,2,4),256>>>(w3, x2, b3, nullptr, h3,
        128, 1, 128,1, N,1, N, 0, 128*N, 256*N);
    bn_stats<<<256,256>>>(h3, 256);
    bn_apply<<<(256*NNV+255)/256,256>>>(h3, g3, be3, 256);

    // 5) Q, K, V projections (256->128) on tensor cores
    gemm_tc<true,false,0><<<dim3(32,1,4),256>>>(qw, h3, qb, nullptr, Qp,
        256, 1, 256,1, N,1, N, 0, 256*N, 128*N);
    gemm_tc<true,false,0><<<dim3(32,1,4),256>>>(kw, h3, kb, nullptr, Kp,
        256, 1, 256,1, N,1, N, 0, 256*N, 128*N);
    gemm_tc<true,false,0><<<dim3(32,1,4),256>>>(vw, h3, vb, nullptr, Vp,
        256, 1, 256,1, N,1, N, 0, 256*N, 128*N);

    // 6) S = Q^T K via tensor cores
    gemm_tc<false,false,0><<<dim3(32,32,4),256>>>(Qp, Kp, nullptr, nullptr, Sp,
        128, 1, 1,N, N,1, N, 128*N, 128*N, (long long)N*N);

    // 7) softmax over m
    softmax_row<<<16384,256>>>(Sp);

    // 8) O = V · P^T via tensor cores, k-split x8 + deterministic reduce
    gemm_tc<true,true,0><<<dim3(32,1,32),256>>>(Vp, Sp, nullptr, nullptr, P8,
        512, 8, N,1, 1,N, N, 128*N, (long long)N*N, 128*N);
    reduce8<<<(BV*128*NV)/256, 256>>>(P8, Op);

    // 9) h4 = conv(O, fw) + fb + h3 (residual) on tensor cores
    gemm_tc<true,false,0><<<dim3(32,2,4),256>>>(fw, Op, fb, h3, h4,
        128, 1, 128,1, N,1, N, 0, 128*N, 256*N);

    // 10) a = relu(conv(h4, aw1))  (M=64: stays on 64x64 fp32 kernel)
    gemm_k<false,false,1><<<dim3(64,1,4),256>>>(aw1, h4, ab1, nullptr, ap,
        64, 256, 256,1, N,1, N, 0, 256*N, 64*N);

    // 11) scores, softmax over n, weighted pool, final FC
    score_kernel<<<64,256>>>(ap, aw2, ab2, sp);
    softmax_row<<<4,256>>>(sp);
    pool_kernel<<<dim3(256,4),256>>>(h4, sp, pp);
    fc_kernel<<<4,256>>>(pp, fcw, fcb, out);
}

// round 14
// speedup vs baseline: 1.5966x; 1.0435x over previous
#include <cuda_runtime.h>
#include <cuda_bf16.h>
#include <math.h>

#define BV 4
#define NV 4096
#define NNV (BV*NV)

// ---------------- scratch (device globals; no allocation allowed) ----------
__device__ float g_h18[(size_t)BV*18*NV];
__device__ float g_x1 [(size_t)BV*64*NV];
__device__ float g_x2 [(size_t)BV*128*NV];
__device__ float g_h3 [(size_t)BV*256*NV];
__device__ float g_Q  [(size_t)BV*128*NV];
__device__ float g_Kt [(size_t)BV*128*NV];
__device__ float g_V  [(size_t)BV*128*NV];
__device__ float g_O  [(size_t)BV*128*NV];
__device__ float g_S  [(size_t)BV*NV*NV];      // 268 MB attention logits
__device__ float g_P8 [(size_t)BV*8*128*NV];   // 64 MB k-split partials for O
__device__ float g_rm [(size_t)BV*NV];         // per-row max of S
__device__ float g_rli[(size_t)BV*NV];         // per-row 1/sum(exp(S-m))
__device__ float g_h4 [(size_t)BV*256*NV];
__device__ float g_a  [(size_t)BV*64*NV];
__device__ float g_sc [(size_t)BV*NV];
__device__ float g_mean[256];
__device__ float g_rstd[256];
__device__ float g_pooled[BV*256];

// ---------------- KNN + local diffs ----------------------------------------
__global__ void knn_kernel(const float* __restrict__ x)
{
    __shared__ float sx[NV], sy[NV], sz[NV];
    int b = blockIdx.y;
    const float* xb = x + (size_t)b * NV * 9;
    for (int m = threadIdx.x; m < NV; m += blockDim.x) {
        sx[m] = xb[(size_t)m*9 + 0];
        sy[m] = xb[(size_t)m*9 + 1];
        sz[m] = xb[(size_t)m*9 + 2];
    }
    __syncthreads();

    int n = blockIdx.x * blockDim.x + threadIdx.x;
    float qx = sx[n], qy = sy[n], qz = sz[n];
    float qs = fmaf(qz, qz, fmaf(qy, qy, qx*qx));

    float bd[9]; int bi[9];
#pragma unroll
    for (int j = 0; j < 9; j++) { bd[j] = 3.4e38f; bi[j] = 0; }

#pragma unroll 4
    for (int m = 0; m < NV; m++) {
        float mx = sx[m], my = sy[m], mz = sz[m];
        float ms  = fmaf(mz, mz, fmaf(my, my, mx*mx));
        float dot = fmaf(mz, qz, fmaf(my, qy, mx*qx));
        float d2  = fmaf(-2.f, dot, qs + ms);
        d2 = fmaxf(d2, 0.f);
        if (d2 < bd[8]) {
            bool pl = false;
#pragma unroll
            for (int j = 8; j >= 1; j--) {
                if (!pl) {
                    if (d2 < bd[j-1]) { bd[j] = bd[j-1]; bi[j] = bi[j-1]; }
                    else              { bd[j] = d2;      bi[j] = m; pl = true; }
                }
            }
            if (!pl) { bd[0] = d2; bi[0] = m; }
        }
    }

    float acc[9];
#pragma unroll
    for (int c = 0; c < 9; c++) acc[c] = 0.f;
#pragma unroll
    for (int j = 1; j < 9; j++) {
        const float* xr = xb + (size_t)bi[j] * 9;
#pragma unroll
        for (int c = 0; c < 9; c++) acc[c] += xr[c];
    }
    const float* xn = xb + (size_t)n * 9;
#pragma unroll
    for (int c = 0; c < 9; c++) {
        float xc = xn[c];
        g_h18[((size_t)b*18 + c    )*NV + n] = acc[c]*0.125f - xc;
        g_h18[((size_t)b*18 + 9 + c)*NV + n] = xc;
    }
}

// ---------------- generic tiled GEMM (64x64, small/odd shapes) --------------
template<bool AKI, bool BKI, int ACT>
__global__ void __launch_bounds__(256)
gemm_k(const float* __restrict__ A, const float* __restrict__ B,
       const float* __restrict__ bias, const float* __restrict__ res,
       float* __restrict__ C,
       int M, int K,
       long long sAi, long long sAk, long long sBk, long long sBj,
       long long ldC, long long bA, long long bB, long long bC)
{
    __shared__ __align__(16) float As[16*66];
    __shared__ __align__(16) float Bs[16*66];
    int b  = blockIdx.z;
    const float* Ab = A + (long long)b * bA;
    const float* Bb = B + (long long)b * bB;
    float* Cb = C + (long long)b * bC;
    int i0 = blockIdx.y * 64, j0 = blockIdx.x * 64;
    int tid = threadIdx.x;
    int tx = tid & 15, ty = tid >> 4;

    float acc[4][4];
#pragma unroll
    for (int r = 0; r < 4; r++)
#pragma unroll
        for (int c = 0; c < 4; c++) acc[r][c] = 0.f;

    for (int k0 = 0; k0 < K; k0 += 16) {
#pragma unroll
        for (int l = 0; l < 4; l++) {
            int t = tid + l*256;
            int kc, ii;
            if (AKI) { ii = t >> 4; kc = t & 15; } else { kc = t >> 6; ii = t & 63; }
            float av = 0.f;
            if (k0 + kc < K) av = Ab[(long long)(i0+ii)*sAi + (long long)(k0+kc)*sAk];
            As[kc*66 + ii] = av;
            int jj;
            if (BKI) { jj = t >> 4; kc = t & 15; } else { kc = t >> 6; jj = t & 63; }
            float bv = 0.f;
            if (k0 + kc < K) bv = Bb[(long long)(k0+kc)*sBk + (long long)(j0+jj)*sBj];
            Bs[kc*66 + jj] = bv;
        }
        __syncthreads();
#pragma unroll
        for (int kc = 0; kc < 16; kc++) {
            float2 a0 = *(const float2*)&As[kc*66 + ty*4];
            float2 a1 = *(const float2*)&As[kc*66 + ty*4 + 2];
            float2 b0 = *(const float2*)&Bs[kc*66 + tx*4];
            float2 b1 = *(const float2*)&Bs[kc*66 + tx*4 + 2];
            float ar[4] = {a0.x, a0.y, a1.x, a1.y};
            float br[4] = {b0.x, b0.y, b1.x, b1.y};
#pragma unroll
            for (int r = 0; r < 4; r++)
#pragma unroll
                for (int c = 0; c < 4; c++)
                    acc[r][c] = fmaf(ar[r], br[c], acc[r][c]);
        }
        __syncthreads();
    }

#pragma unroll
    for (int r = 0; r < 4; r++) {
        int i = i0 + ty*4 + r;
        float bv = bias ? bias[i] : 0.f;
#pragma unroll
        for (int c = 0; c < 4; c++) {
            int j = j0 + tx*4 + c;
            float v = acc[r][c] + bv;
            if (res) v += res[(long long)b*bC + (long long)i*ldC + j];
            if (ACT == 1) v = fmaxf(v, 0.f);
            Cb[(long long)i*ldC + j] = v;
        }
    }
}

// ---------------- tensor-core GEMM (split-bf16 x3, m16n8k16 HMMA) -----------
// C[z][i][j] = sum_k A[i,k]*B[k,j] (+bias[i] +res, opt ReLU), fp32 in/out,
// ~fp32 accuracy via hi/lo bf16 decomposition (hi*hi + hi*lo + lo*hi).
// Block tile 128x128, k-chunk 32. 8 warps: wi=w&3 (32 rows), wj=w>>2 (64 cols).
// KS%32==0, dims %128==0.
// Contract: AKI => unit k-stride for A (sAk==1); !AKI => unit i-stride (sAi==1).
//           BKI => unit k-stride for B (sBk==1); !BKI => unit j-stride (sBj==1).
// SOFT==1 (requires BKI): B elements transformed p = expf(s-m[row])*li[row]
// during staging, with per-row stats rm/rli indexed [b*NV + j].
__device__ __forceinline__ void mma16816(float* c, const unsigned* a,
                                         unsigned b0, unsigned b1)
{
    asm volatile(
        "mma.sync.aligned.m16n8k16.row.col.f32.bf16.bf16.f32 "
        "{%0,%1,%2,%3},{%4,%5,%6,%7},{%8,%9},{%0,%1,%2,%3};"
        : "+f"(c[0]), "+f"(c[1]), "+f"(c[2]), "+f"(c[3])
        : "r"(a[0]), "r"(a[1]), "r"(a[2]), "r"(a[3]), "r"(b0), "r"(b1));
}

__device__ __forceinline__ void ldsm4(unsigned& r0, unsigned& r1,
                                      unsigned& r2, unsigned& r3, unsigned addr)
{
    asm volatile("ldmatrix.sync.aligned.m8n8.x4.shared.b16 {%0,%1,%2,%3},[%4];"
                 : "=r"(r0), "=r"(r1), "=r"(r2), "=r"(r3) : "r"(addr));
}

__device__ __forceinline__ unsigned pack2bf(__nv_bfloat16 a, __nv_bfloat16 b)
{
    return (unsigned)__bfloat16_as_ushort(a) |
           ((unsigned)__bfloat16_as_ushort(b) << 16);
}

#define TCPAD 40   // bf16 elems per smem row (32 data + 8 pad; 80B stride)

// Stage one 128x32 fp32 tile into hi/lo bf16 smem arrays.
// KI=true : k unit-stride in gmem -> float4 along k, STS.64.
// KI=false: row unit-stride in gmem -> 16 consecutive k per thread, STS.128.
// SOFT: apply softmax transform using row stats (KI path only).
template<bool KI, int SOFT>
__device__ __forceinline__ void stage_tile(
    const float* __restrict__ src, long long sRow, long long sK,
    int row0, int kb, int tid,
    __nv_bfloat16 (*Sh)[TCPAD], __nv_bfloat16 (*Sl)[TCPAD],
    const float* __restrict__ rm, const float* __restrict__ rli)
{
    if (KI) {
        int kg = (tid & 7) * 4;
        int rb = tid >> 3;                         // 0..31
#pragma unroll
        for (int p = 0; p < 4; p++) {
            int r = rb + p*32;
            float4 v = *(const float4*)(src + (long long)(row0+r)*sRow + (kb+kg));
            if (SOFT) {
                float mm = rm[row0 + r];
                float li = rli[row0 + r];
                v.x = expf(v.x - mm) * li;
                v.y = expf(v.y - mm) * li;
                v.z = expf(v.z - mm) * li;
                v.w = expf(v.w - mm) * li;
            }
            __nv_bfloat16 h0 = __float2bfloat16(v.x), h1 = __float2bfloat16(v.y);
            __nv_bfloat16 h2 = __float2bfloat16(v.z), h3 = __float2bfloat16(v.w);
            uint2 hh = make_uint2(pack2bf(h0,h1), pack2bf(h2,h3));
            uint2 ll = make_uint2(
                pack2bf(__float2bfloat16(v.x - __bfloat162float(h0)),
                        __float2bfloat16(v.y - __bfloat162float(h1))),
                pack2bf(__float2bfloat16(v.z - __bfloat162float(h2)),
                        __float2bfloat16(v.w - __bfloat162float(h3))));
            *(uint2*)&Sh[r][kg] = hh;
            *(uint2*)&Sl[r][kg] = ll;
        }
    } else {
        int r  = tid & 127;
        int kh = (tid >> 7) * 16;                  // 0 or 16
        const float* sp = src + (long long)(row0+r) + (long long)(kb+kh)*sK;
        unsigned hw[8], lw[8];
#pragma unroll
        for (int q = 0; q < 8; q++) {
            float v0 = sp[(long long)(2*q  )*sK];
            float v1 = sp[(long long)(2*q+1)*sK];
            __nv_bfloat16 h0 = __float2bfloat16(v0), h1 = __float2bfloat16(v1);
            hw[q] = pack2bf(h0, h1);
            lw[q] = pack2bf(__float2bfloat16(v0 - __bfloat162float(h0)),
                            __float2bfloat16(v1 - __bfloat162float(h1)));
        }
        *(uint4*)&Sh[r][kh]     = make_uint4(hw[0], hw[1], hw[2], hw[3]);
        *(uint4*)&Sh[r][kh + 8] = make_uint4(hw[4], hw[5], hw[6], hw[7]);
        *(uint4*)&Sl[r][kh]     = make_uint4(lw[0], lw[1], lw[2], lw[3]);
        *(uint4*)&Sl[r][kh + 8] = make_uint4(lw[4], lw[5], lw[6], lw[7]);
    }
}

template<bool AKI, bool BKI, int ACT, int SOFT>
__global__ void __launch_bounds__(256, 2)
gemm_tc(const float* __restrict__ A, const float* __restrict__ B,
        const float* __restrict__ bias, const float* __restrict__ res,
        float* __restrict__ C,
        int KS, int NS,
        long long sAi, long long sAk, long long sBk, long long sBj,
        long long ldC, long long bA, long long bB, long long bCz,
        const float* __restrict__ rm, const float* __restrict__ rli)
{
    __shared__ __align__(16) __nv_bfloat16 Ah[128][TCPAD];
    __shared__ __align__(16) __nv_bfloat16 Al[128][TCPAD];
    __shared__ __align__(16) __nv_bfloat16 Bh[128][TCPAD];
    __shared__ __align__(16) __nv_bfloat16 Bl[128][TCPAD];

    int bz = blockIdx.z;
    int b  = bz / NS;
    int s  = bz - b * NS;
    const float* Ab = A + (long long)b * bA;
    const float* Bb = B + (long long)b * bB;
    float* Cb = C + (long long)bz * bCz;
    int i0 = blockIdx.y * 128, j0 = blockIdx.x * 128;
    int kstart = s * KS;
    int tid  = threadIdx.x;
    int lane = tid & 31;
    int w    = tid >> 5;
    int wi   = w & 3;            // 4 warps over i: 32 rows each
    int wj   = w >> 2;           // 2 warps over j: 64 cols each
    int lg = lane >> 3, lr = lane & 7;

    // per-batch row-stat base for the softmax-staged B (rows indexed by j)
    const float* rmB  = SOFT ? (rm  + (long long)b * NV) : nullptr;
    const float* rliB = SOFT ? (rli + (long long)b * NV) : nullptr;

    float acc[2][8][4];
#pragma unroll
    for (int mt = 0; mt < 2; mt++)
#pragma unroll
        for (int nt = 0; nt < 8; nt++)
#pragma unroll
            for (int q = 0; q < 4; q++) acc[mt][nt][q] = 0.f;

    for (int k0 = 0; k0 < KS; k0 += 32) {
        int kb = kstart + k0;
        // stage A (row dim = i): strides (sAi over rows, sAk over k)
        stage_tile<AKI, 0>(Ab, sAi, sAk, i0, kb, tid, Ah, Al, nullptr, nullptr);
        // stage B (row dim = j): strides (sBj over rows, sBk over k)
        stage_tile<BKI, SOFT>(Bb, sBj, sBk, j0, kb, tid, Bh, Bl, rmB, rliB);
        __syncthreads();

#pragma unroll
        for (int kt = 0; kt < 32; kt += 16) {
            unsigned ah[2][4], al[2][4];
#pragma unroll
            for (int mt = 0; mt < 2; mt++) {
                int row = wi*32 + mt*16 + (lg & 1)*8 + lr;
                int col = kt + (lg >> 1)*8;
                ldsm4(ah[mt][0], ah[mt][1], ah[mt][2], ah[mt][3],
                      (unsigned)__cvta_generic_to_shared(&Ah[row][col]));
                ldsm4(al[mt][0], al[mt][1], al[mt][2], al[mt][3],
                      (unsigned)__cvta_generic_to_shared(&Al[row][col]));
            }
#pragma unroll
            for (int nt2 = 0; nt2 < 4; nt2++) {
                int row = wj*64 + nt2*16 + (lg >> 1)*8 + lr;
                int col = kt + (lg & 1)*8;
                unsigned bh[4], bl[4];
                ldsm4(bh[0], bh[1], bh[2], bh[3],
                      (unsigned)__cvta_generic_to_shared(&Bh[row][col]));
                ldsm4(bl[0], bl[1], bl[2], bl[3],
                      (unsigned)__cvta_generic_to_shared(&Bl[row][col]));
#pragma unroll
                for (int mt = 0; mt < 2; mt++) {
                    mma16816(acc[mt][nt2*2+0], ah[mt], bh[0], bh[1]);
                    mma16816(acc[mt][nt2*2+0], ah[mt], bl[0], bl[1]);
                    mma16816(acc[mt][nt2*2+0], al[mt], bh[0], bh[1]);
                    mma16816(acc[mt][nt2*2+1], ah[mt], bh[2], bh[3]);
                    mma16816(acc[mt][nt2*2+1], ah[mt], bl[2], bl[3]);
                    mma16816(acc[mt][nt2*2+1], al[mt], bh[2], bh[3]);
                }
            }
        }
        __syncthreads();
    }

    // epilogue: bias / residual / ReLU
    int r0 = lane >> 2, cc = (lane & 3) * 2;
#pragma unroll
    for (int mt = 0; mt < 2; mt++) {
        int i = i0 + wi*32 + mt*16 + r0;
        float bv0 = bias ? bias[i]     : 0.f;
        float bv1 = bias ? bias[i + 8] : 0.f;
#pragma unroll
        for (int nt = 0; nt < 8; nt++) {
            int j = j0 + wj*64 + nt*8 + cc;
            float v0 = acc[mt][nt][0] + bv0;
            float v1 = acc[mt][nt][1] + bv0;
            float v2 = acc[mt][nt][2] + bv1;
            float v3 = acc[mt][nt][3] + bv1;
            if (res) {
                const float* rp = res + (long long)bz*bCz;
                v0 += rp[(long long)i*ldC + j];
                v1 += rp[(long long)i*ldC + j + 1];
                v2 += rp[(long long)(i+8)*ldC + j];
                v3 += rp[(long long)(i+8)*ldC + j + 1];
            }
            if (ACT == 1) {
                v0 = fmaxf(v0, 0.f); v1 = fmaxf(v1, 0.f);
                v2 = fmaxf(v2, 0.f); v3 = fmaxf(v3, 0.f);
            }
            *(float2*)&Cb[(long long)i*ldC + j]     = make_float2(v0, v1);
            *(float2*)&Cb[(long long)(i+8)*ldC + j] = make_float2(v2, v3);
        }
    }
}

// ---------------- deterministic k-split reduction for O ----------------------
__global__ void reduce8(const float* __restrict__ part, float* __restrict__ O)
{
    int idx = blockIdx.x * 256 + threadIdx.x;
    int b   = idx >> 19;
    int off = idx & ((1 << 19) - 1);
    const float* p = part + ((long long)b * 8) * (128LL * NV) + off;
    float acc = 0.f;
#pragma unroll
    for (int s = 0; s < 8; s++) acc += p[(long long)s * 128 * NV];
    O[idx] = acc;
}

// ---------------- BN statistics (fp64, deterministic) -----------------------
__global__ void bn_stats(const float* __restrict__ y, int Co)
{
    int ch = blockIdx.x, tid = threadIdx.x;
    double s = 0.0, s2 = 0.0;
    for (int t = tid; t < NNV; t += 256) {
        int b = t >> 12, n = t & 4095;
        float v = y[((size_t)b*Co + ch)*NV + n];
        s += v; s2 += (double)v * (double)v;
    }
    __shared__ double rs[256], rq[256];
    rs[tid] = s; rq[tid] = s2; __syncthreads();
    for (int st = 128; st > 0; st >>= 1) {
        if (tid < st) { rs[tid] += rs[tid+st]; rq[tid] += rq[tid+st]; }
        __syncthreads();
    }
    if (tid == 0) {
        double m = rs[0] / (double)NNV;
        double var = rq[0] / (double)NNV - m*m;
        g_mean[ch] = (float)m;
        g_rstd[ch] = (float)(1.0 / sqrt(var + 1e-5));
    }
}

__global__ void bn_apply(float* __restrict__ y, const float* __restrict__ gm,
                         const float* __restrict__ bt, int Co)
{
    int idx = blockIdx.x * 256 + threadIdx.x;
    if (idx >= Co * NNV) return;
    int ch = (idx >> 12) % Co;
    float v = y[idx];
    v = gm[ch] * (v - g_mean[ch]) * g_rstd[ch] + bt[ch];
    y[idx] = fmaxf(v, 0.f);
}

// ---------------- per-row softmax stats over 4096 (max, 1/sum) --------------
__global__ void row_stats(const float* __restrict__ S,
                          float* __restrict__ rm, float* __restrict__ rli)
{
    const float* p = S + (size_t)blockIdx.x * 4096;
    int tid = threadIdx.x;
    float v[16];
    float mx = -3.4e38f;
#pragma unroll
    for (int l = 0; l < 16; l++) { v[l] = p[tid + l*256]; mx = fmaxf(mx, v[l]); }
    __shared__ float red[256];
    red[tid] = mx; __syncthreads();
    for (int s = 128; s > 0; s >>= 1) {
        if (tid < s) red[tid] = fmaxf(red[tid], red[tid+s]);
        __syncthreads();
    }
    mx = red[0]; __syncthreads();
    float sum = 0.f;
#pragma unroll
    for (int l = 0; l < 16; l++) sum += expf(v[l] - mx);
    red[tid] = sum; __syncthreads();
    for (int s = 128; s > 0; s >>= 1) {
        if (tid < s) red[tid] += red[tid+s];
        __syncthreads();
    }
    if (tid == 0) {
        rm[blockIdx.x]  = mx;
        rli[blockIdx.x] = 1.0f / red[0];
    }
}

// ---------------- row softmax over 4096 (in place, tail use) -----------------
__global__ void softmax_row(float* __restrict__ S)
{
    float* p = S + (size_t)blockIdx.x * 4096;
    int tid = threadIdx.x;
    float v[16];
    float mx = -3.4e38f;
#pragma unroll
    for (int l = 0; l < 16; l++) { v[l] = p[tid + l*256]; mx = fmaxf(mx, v[l]); }
    __shared__ float red[256];
    red[tid] = mx; __syncthreads();
    for (int s = 128; s > 0; s >>= 1) {
        if (tid < s) red[tid] = fmaxf(red[tid], red[tid+s]);
        __syncthreads();
    }
    mx = red[0]; __syncthreads();
    float sum = 0.f;
#pragma unroll
    for (int l = 0; l < 16; l++) { v[l] = expf(v[l] - mx); sum += v[l]; }
    red[tid] = sum; __syncthreads();
    for (int s = 128; s > 0; s >>= 1) {
        if (tid < s) red[tid] += red[tid+s];
        __syncthreads();
    }
    float inv = 1.0f / red[0];
#pragma unroll
    for (int l = 0; l < 16; l++) p[tid + l*256] = v[l] * inv;
}

// ---------------- attention-pool tail ----------------------------------------
__global__ void score_kernel(const float* __restrict__ a, const float* __restrict__ aw2,
                             const float* __restrict__ ab2, float* __restrict__ s)
{
    int t = blockIdx.x * 256 + threadIdx.x;
    int b = t >> 12, n = t & 4095;
    float acc = ab2[0];
#pragma unroll 8
    for (int c = 0; c < 64; c++) acc += aw2[c] * a[((size_t)b*64 + c)*NV + n];
    s[t] = acc;
}

__global__ void pool_kernel(const float* __restrict__ h, const float* __restrict__ w,
                            float* __restrict__ pooled)
{
    int c = blockIdx.x, b = blockIdx.y, tid = threadIdx.x;
    const float* hp = h + ((size_t)b*256 + c)*NV;
    const float* wp = w + (size_t)b*NV;
    float acc = 0.f;
    for (int n = tid; n < NV; n += 256) acc = fmaf(hp[n], wp[n], acc);
    __shared__ float red[256];
    red[tid] = acc; __syncthreads();
    for (int s = 128; s > 0; s >>= 1) {
        if (tid < s) red[tid] += red[tid+s];
        __syncthreads();
    }
    if (tid == 0) pooled[b*256 + c] = red[0];
}

__global__ void fc_kernel(const float* __restrict__ pooled, const float* __restrict__ fcw,
                          const float* __restrict__ fcb, float* __restrict__ out)
{
    int b = blockIdx.x, j = threadIdx.x;
    __shared__ float sp[256];
    sp[j] = pooled[b*256 + j]; __syncthreads();
    float acc = fcb[j];
#pragma unroll 8
    for (int c = 0; c < 256; c++) acc = fmaf(sp[c], fcw[j*256 + c], acc);
    out[b*256 + j] = fmaxf(acc, 0.f);
}

// ---------------- host launch ------------------------------------------------
static float* sym_addr(const void* s)
{
    void* p = nullptr;
    cudaGetSymbolAddress(&p, s);
    return (float*)p;
}

extern "C" void kernel_launch(void* const* d_in, const int* in_sizes, int n_in,
                              void* d_out, int out_size)
{
    const float* x   = (const float*)d_in[0];
    const float* w1  = (const float*)d_in[1];
    const float* b1  = (const float*)d_in[2];
    const float* g1  = (const float*)d_in[3];
    const float* be1 = (const float*)d_in[4];
    const float* w2  = (const float*)d_in[5];
    const float* b2  = (const float*)d_in[6];
    const float* g2  = (const float*)d_in[7];
    const float* be2 = (const float*)d_in[8];
    const float* w3  = (const float*)d_in[9];
    const float* b3  = (const float*)d_in[10];
    const float* g3  = (const float*)d_in[11];
    const float* be3 = (const float*)d_in[12];
    const float* qw  = (const float*)d_in[13];
    const float* qb  = (const float*)d_in[14];
    const float* kw  = (const float*)d_in[15];
    const float* kb  = (const float*)d_in[16];
    const float* vw  = (const float*)d_in[17];
    const float* vb  = (const float*)d_in[18];
    const float* fw  = (const float*)d_in[19];
    const float* fb  = (const float*)d_in[20];
    const float* aw1 = (const float*)d_in[21];
    const float* ab1 = (const float*)d_in[22];
    const float* aw2 = (const float*)d_in[23];
    const float* ab2 = (const float*)d_in[24];
    const float* fcw = (const float*)d_in[25];
    const float* fcb = (const float*)d_in[26];
    float* out = (float*)d_out;

    float* h18 = sym_addr(g_h18);
    float* x1  = sym_addr(g_x1);
    float* x2  = sym_addr(g_x2);
    float* h3  = sym_addr(g_h3);
    float* Qp  = sym_addr(g_Q);
    float* Kp  = sym_addr(g_Kt);
    float* Vp  = sym_addr(g_V);
    float* Op  = sym_addr(g_O);
    float* Sp  = sym_addr(g_S);
    float* P8  = sym_addr(g_P8);
    float* rmp = sym_addr(g_rm);
    float* rlp = sym_addr(g_rli);
    float* h4  = sym_addr(g_h4);
    float* ap  = sym_addr(g_a);
    float* sp  = sym_addr(g_sc);
    float* pp  = sym_addr(g_pooled);

    const long long N = NV;

    // 1) KNN + local diff features
    knn_kernel<<<dim3(16, 4), 256>>>(x);

    // 2) conv1 (18->64) + BN + ReLU (K=18: stays on 64x64 fp32 kernel)
    gemm_k<false,false,0><<<dim3(64,1,4),256>>>(w1, h18, b1, nullptr, x1,
        64, 18, 18,1, N,1, N, 0, 18*N, 64*N);
    bn_stats<<<64,256>>>(x1, 64);
    bn_apply<<<(64*NNV+255)/256,256>>>(x1, g1, be1, 64);

    // 3) conv2 (64->128) on tensor cores
    gemm_tc<true,false,0,0><<<dim3(32,1,4),256>>>(w2, x1, b2, nullptr, x2,
        64, 1, 64,1, N,1, N, 0, 64*N, 128*N, nullptr, nullptr);
    bn_stats<<<128,256>>>(x2, 128);
    bn_apply<<<(128*NNV+255)/256,256>>>(x2, g2, be2, 128);

    // 4) conv3 (128->256) on tensor cores
    gemm_tc<true,false,0,0><<<dim3(32,2,4),256>>>(w3, x2, b3, nullptr, h3,
        128, 1, 128,1, N,1, N, 0, 128*N, 256*N, nullptr, nullptr);
    bn_stats<<<256,256>>>(h3, 256);
    bn_apply<<<(256*NNV+255)/256,256>>>(h3, g3, be3, 256);

    // 5) Q, K, V projections (256->128) on tensor cores
    gemm_tc<true,false,0,0><<<dim3(32,1,4),256>>>(qw, h3, qb, nullptr, Qp,
        256, 1, 256,1, N,1, N, 0, 256*N, 128*N, nullptr, nullptr);
    gemm_tc<true,false,0,0><<<dim3(32,1,4),256>>>(kw, h3, kb, nullptr, Kp,
        256, 1, 256,1, N,1, N, 0, 256*N, 128*N, nullptr, nullptr);
    gemm_tc<true,false,0,0><<<dim3(32,1,4),256>>>(vw, h3, vb, nullptr, Vp,
        256, 1, 256,1, N,1, N, 0, 256*N, 128*N, nullptr, nullptr);

    // 6) S = Q^T K via tensor cores (logits only; no softmax write-back)
    gemm_tc<false,false,0,0><<<dim3(32,32,4),256>>>(Qp, Kp, nullptr, nullptr, Sp,
        128, 1, 1,N, N,1, N, 128*N, 128*N, (long long)N*N, nullptr, nullptr);

    // 7) per-row softmax stats (max, 1/sum) — S itself is left untouched
    row_stats<<<16384,256>>>(Sp, rmp, rlp);

    // 8) O = V · softmax(S)^T via tensor cores with exp fused into B staging,
    //    k-split x8 + deterministic reduce
    gemm_tc<true,true,0,1><<<dim3(32,1,32),256>>>(Vp, Sp, nullptr, nullptr, P8,
        512, 8, N,1, 1,N, N, 128*N, (long long)N*N, 128*N, rmp, rlp);
    reduce8<<<(BV*128*NV)/256, 256>>>(P8, Op);

    // 9) h4 = conv(O, fw) + fb + h3 (residual) on tensor cores
    gemm_tc<true,false,0,0><<<dim3(32,2,4),256>>>(fw, Op, fb, h3, h4,
        128, 1, 128,1, N,1, N, 0, 128*N, 256*N, nullptr, nullptr);

    // 10) a = relu(conv(h4, aw1))  (M=64: stays on 64x64 fp32 kernel)
    gemm_k<false,false,1><<<dim3(64,1,4),256>>>(aw1, h4, ab1, nullptr, ap,
        64, 256, 256,1, N,1, N, 0, 256*N, 64*N);

    // 11) scores, softmax over n, weighted pool, final FC
    score_kernel<<<64,256>>>(ap, aw2, ab2, sp);
    softmax_row<<<4,256>>>(sp);
    pool_kernel<<<dim3(256,4),256>>>(h4, sp, pp);
    fc_kernel<<<4,256>>>(pp, fcw, fcb, out);
}